// round 5
// baseline (speedup 1.0000x reference)
#include <cuda_runtime.h>
#include <cuda_bf16.h>
#include <cuda_fp16.h>
#include <math.h>
#include <stdint.h>

#define DM   1024
#define NSEQ 2048
#define NB   2
#define NH   16
#define HD   64
#define MROWS (NB*NSEQ)          // 4096
#define NELEM ((size_t)MROWS*DM) // 4,194,304
#define WELEM ((size_t)DM*DM)    // 1,048,576

// ---------------- scratch (__device__ globals; no allocations) -------------
__device__ __nv_bfloat16 gXh[3*NELEM];   // split inputs q,k,v
__device__ __nv_bfloat16 gXl[3*NELEM];
__device__ __nv_bfloat16 gWh[4*WELEM];   // split weights Wq,Wk,Wv,Wo
__device__ __nv_bfloat16 gWl[4*WELEM];
__device__ __nv_bfloat16 gQh[NELEM], gQl[NELEM];  // (b,h,n,d), Q pre-scaled
__device__ __nv_bfloat16 gKh[NELEM], gKl[NELEM];
__device__ __half        gVh16[NELEM], gVl16[NELEM]; // V as fp16 pair
__device__ __nv_bfloat16 gOh[NELEM], gOl[NELEM];  // attn out (b*n, h*d)

// ---------------- PTX helpers ---------------------------------------------
__device__ __forceinline__ void mma16816(float* c,
    unsigned a0, unsigned a1, unsigned a2, unsigned a3,
    unsigned b0, unsigned b1)
{
    asm volatile(
        "mma.sync.aligned.m16n8k16.row.col.f32.bf16.bf16.f32 "
        "{%0,%1,%2,%3},{%4,%5,%6,%7},{%8,%9},{%0,%1,%2,%3};"
        : "+f"(c[0]), "+f"(c[1]), "+f"(c[2]), "+f"(c[3])
        : "r"(a0), "r"(a1), "r"(a2), "r"(a3), "r"(b0), "r"(b1));
}

__device__ __forceinline__ void mma16816h(float* c,
    unsigned a0, unsigned a1, unsigned a2, unsigned a3,
    unsigned b0, unsigned b1)
{
    asm volatile(
        "mma.sync.aligned.m16n8k16.row.col.f32.f16.f16.f32 "
        "{%0,%1,%2,%3},{%4,%5,%6,%7},{%8,%9},{%0,%1,%2,%3};"
        : "+f"(c[0]), "+f"(c[1]), "+f"(c[2]), "+f"(c[3])
        : "r"(a0), "r"(a1), "r"(a2), "r"(a3), "r"(b0), "r"(b1));
}

__device__ __forceinline__ void ldm_x4(unsigned& r0, unsigned& r1,
                                       unsigned& r2, unsigned& r3,
                                       const void* p)
{
    unsigned a = (unsigned)__cvta_generic_to_shared(p);
    asm volatile("ldmatrix.sync.aligned.m8n8.x4.shared.b16 {%0,%1,%2,%3},[%4];"
                 : "=r"(r0), "=r"(r1), "=r"(r2), "=r"(r3) : "r"(a));
}

__device__ __forceinline__ void ldm_x2(unsigned& r0, unsigned& r1, const void* p)
{
    unsigned a = (unsigned)__cvta_generic_to_shared(p);
    asm volatile("ldmatrix.sync.aligned.m8n8.x2.shared.b16 {%0,%1},[%2];"
                 : "=r"(r0), "=r"(r1) : "r"(a));
}

__device__ __forceinline__ void ldm_x2t(unsigned& r0, unsigned& r1, const void* p)
{
    unsigned a = (unsigned)__cvta_generic_to_shared(p);
    asm volatile("ldmatrix.sync.aligned.m8n8.x2.trans.shared.b16 {%0,%1},[%2];"
                 : "=r"(r0), "=r"(r1) : "r"(a));
}

__device__ __forceinline__ void cp16(void* dst, const void* src)
{
    unsigned d = (unsigned)__cvta_generic_to_shared(dst);
    asm volatile("cp.async.cg.shared.global [%0], [%1], 16;" :: "r"(d), "l"(src));
}
#define CP_COMMIT() asm volatile("cp.async.commit_group;")
#define CP_WAIT0()  asm volatile("cp.async.wait_group 0;")

// split fp32 pair -> packed bf16x2 hi + bf16x2 lo
__device__ __forceinline__ void split_pack(float x, float y,
                                           unsigned& h, unsigned& l)
{
    __nv_bfloat16 hx = __float2bfloat16(x);
    __nv_bfloat16 hy = __float2bfloat16(y);
    float rx = x - __bfloat162float(hx);
    float ry = y - __bfloat162float(hy);
    __nv_bfloat16 lx = __float2bfloat16(rx);
    __nv_bfloat16 ly = __float2bfloat16(ry);
    h = ((unsigned)__bfloat16_as_ushort(hy) << 16) | __bfloat16_as_ushort(hx);
    l = ((unsigned)__bfloat16_as_ushort(ly) << 16) | __bfloat16_as_ushort(lx);
}

// split fp32 pair -> packed fp16x2 hi + fp16x2 lo
__device__ __forceinline__ void split_pack_h(float x, float y,
                                             unsigned& h, unsigned& l)
{
    __half hx = __float2half_rn(x);
    __half hy = __float2half_rn(y);
    float rx = x - __half2float(hx);
    float ry = y - __half2float(hy);
    __half2 hp = __halves2half2(hx, hy);
    __half2 lp = __halves2half2(__float2half_rn(rx), __float2half_rn(ry));
    h = *(unsigned*)&hp;
    l = *(unsigned*)&lp;
}

__device__ __forceinline__ unsigned pack_h2(float x, float y)
{
    __half2 p = __floats2half2_rn(x, y);
    return *(unsigned*)&p;
}

// 16B-chunk XOR swizzle for 64-col bf16 tiles (row*64 elems + chunk^row&7)
__device__ __forceinline__ int swz64(int r, int c8)
{
    return r * 64 + ((c8 ^ (r & 7)) * 8);
}

// ---------------- merged fp32 -> split bf16 conversion (single launch) -----
#define NF4_IN (NELEM >> 2)   // 2^20 float4 per input tensor
#define NF4_W  (WELEM >> 2)   // 2^18 float4 per weight tensor
#define NF4_TOT (3*NF4_IN + 4*NF4_W)

__global__ void split_all(const float* __restrict__ q, const float* __restrict__ k,
                          const float* __restrict__ v, const float* __restrict__ wq,
                          const float* __restrict__ wk, const float* __restrict__ wv,
                          const float* __restrict__ wo)
{
    for (size_t i = blockIdx.x * blockDim.x + threadIdx.x; i < NF4_TOT;
         i += (size_t)gridDim.x * blockDim.x) {
        const float* src;
        __nv_bfloat16 *h, *l;
        size_t off;
        if (i < 3*NF4_IN) {
            int slot = (int)(i >> 20);
            off = i & (NF4_IN - 1);
            src = (slot == 0) ? q : (slot == 1) ? k : v;
            h = gXh + (size_t)slot * NELEM;
            l = gXl + (size_t)slot * NELEM;
        } else {
            size_t j = i - 3*NF4_IN;
            int slot = (int)(j >> 18);
            off = j & (NF4_W - 1);
            src = (slot == 0) ? wq : (slot == 1) ? wk : (slot == 2) ? wv : wo;
            h = gWh + (size_t)slot * WELEM;
            l = gWl + (size_t)slot * WELEM;
        }
        float4 val = ((const float4*)src)[off];
        unsigned h0, l0, h1, l1;
        split_pack(val.x, val.y, h0, l0);
        split_pack(val.z, val.w, h1, l1);
        ((uint2*)h)[off] = make_uint2(h0, h1);
        ((uint2*)l)[off] = make_uint2(l0, l1);
    }
}

// ---------------- QKV projection GEMM (split bf16 tensor cores) ------------
#define SAPAD 24

__global__ __launch_bounds__(256, 2) void gemm_qkv(
    const float* __restrict__ bq, const float* __restrict__ bk,
    const float* __restrict__ bv)
{
    __shared__ __nv_bfloat16 sA[2][2][128*SAPAD];
    __shared__ __nv_bfloat16 sB[2][2][128*SAPAD];

    const int z = blockIdx.z;
    const __nv_bfloat16* Xh = gXh + (size_t)z * NELEM;
    const __nv_bfloat16* Xl = gXl + (size_t)z * NELEM;
    const __nv_bfloat16* Wh = gWh + (size_t)z * WELEM;
    const __nv_bfloat16* Wl = gWl + (size_t)z * WELEM;
    const float* bias = (z == 0) ? bq : (z == 1) ? bk : bv;
    const float scale = (z == 0) ? 0.125f : 1.0f;

    const int tid = threadIdx.x, lane = tid & 31, warp = tid >> 5;
    const int m0 = blockIdx.y * 128, n0 = blockIdx.x * 128;
    const int wm = (warp & 1) * 64, wn = (warp >> 1) * 32;

    const int lrow = tid >> 1, lch = (tid & 1) * 8;
    const __nv_bfloat16* gAh = Xh + (size_t)(m0 + lrow) * DM + lch;
    const __nv_bfloat16* gAl = Xl + (size_t)(m0 + lrow) * DM + lch;
    const __nv_bfloat16* gBh = Wh + (size_t)(n0 + lrow) * DM + lch;
    const __nv_bfloat16* gBl = Wl + (size_t)(n0 + lrow) * DM + lch;
    const int so = lrow * SAPAD + lch;

    float c[4][4][4];
    #pragma unroll
    for (int i = 0; i < 4; i++)
        #pragma unroll
        for (int j = 0; j < 4; j++)
            #pragma unroll
            for (int r = 0; r < 4; r++) c[i][j][r] = 0.0f;

    cp16(&sA[0][0][so], gAh); cp16(&sA[0][1][so], gAl);
    cp16(&sB[0][0][so], gBh); cp16(&sB[0][1][so], gBl);
    CP_COMMIT();

    const int ar = lane & 15, ac = (lane >> 4) * 8;
    const int br = lane & 7,  bc = ((lane >> 3) & 1) * 8;

    for (int kt = 0; kt < 64; kt++) {
        const int st = kt & 1;
        CP_WAIT0();
        __syncthreads();
        if (kt < 63) {
            int ko = (kt + 1) * 16;
            cp16(&sA[st ^ 1][0][so], gAh + ko); cp16(&sA[st ^ 1][1][so], gAl + ko);
            cp16(&sB[st ^ 1][0][so], gBh + ko); cp16(&sB[st ^ 1][1][so], gBl + ko);
            CP_COMMIT();
        }

        unsigned bhf[4][2], blf[4][2];
        #pragma unroll
        for (int ni = 0; ni < 4; ni++) {
            int off = (wn + ni * 8 + br) * SAPAD + bc;
            ldm_x2(bhf[ni][0], bhf[ni][1], &sB[st][0][off]);
            ldm_x2(blf[ni][0], blf[ni][1], &sB[st][1][off]);
        }
        #pragma unroll
        for (int mi = 0; mi < 4; mi++) {
            unsigned ah[4], al[4];
            int off = (wm + mi * 16 + ar) * SAPAD + ac;
            ldm_x4(ah[0], ah[1], ah[2], ah[3], &sA[st][0][off]);
            ldm_x4(al[0], al[1], al[2], al[3], &sA[st][1][off]);
            #pragma unroll
            for (int ni = 0; ni < 4; ni++) {
                mma16816(c[mi][ni], ah[0], ah[1], ah[2], ah[3], bhf[ni][0], bhf[ni][1]);
                mma16816(c[mi][ni], ah[0], ah[1], ah[2], ah[3], blf[ni][0], blf[ni][1]);
                mma16816(c[mi][ni], al[0], al[1], al[2], al[3], bhf[ni][0], bhf[ni][1]);
            }
        }
    }

    // epilogue: + bias, * scale(Q), split, scatter to (b,h,n,d)
    const int r0 = lane >> 2, cq = (lane & 3) * 2;
    #pragma unroll
    for (int mi = 0; mi < 4; mi++) {
        #pragma unroll
        for (int ni = 0; ni < 4; ni++) {
            int col = n0 + wn + ni * 8 + cq;
            float b0 = bias[col], b1 = bias[col + 1];
            int hh = col >> 6, d = col & 63;
            #pragma unroll
            for (int half = 0; half < 2; half++) {
                int row = m0 + wm + mi * 16 + r0 + half * 8;
                float v0 = (c[mi][ni][half * 2 + 0] + b0) * scale;
                float v1 = (c[mi][ni][half * 2 + 1] + b1) * scale;
                int bb = row >> 11, n = row & (NSEQ - 1);
                size_t idx = (((size_t)(bb * NH + hh)) * NSEQ + n) * HD + d;
                unsigned ph, pl;
                if (z == 2) {
                    split_pack_h(v0, v1, ph, pl);
                    *(unsigned*)&gVh16[idx] = ph;
                    *(unsigned*)&gVl16[idx] = pl;
                } else {
                    split_pack(v0, v1, ph, pl);
                    if (z == 0) { *(unsigned*)&gQh[idx] = ph; *(unsigned*)&gQl[idx] = pl; }
                    else        { *(unsigned*)&gKh[idx] = ph; *(unsigned*)&gKl[idx] = pl; }
                }
            }
        }
    }
}

// ---------------- output projection GEMM (split bf16, 3-term) --------------
__global__ __launch_bounds__(256, 2) void gemm_out(
    const float* __restrict__ bo, float* __restrict__ out)
{
    __shared__ __nv_bfloat16 sA[2][2][128*SAPAD];
    __shared__ __nv_bfloat16 sB[2][2][128*SAPAD];

    const __nv_bfloat16* Wh = gWh + 3 * WELEM;
    const __nv_bfloat16* Wl = gWl + 3 * WELEM;

    const int tid = threadIdx.x, lane = tid & 31, warp = tid >> 5;
    const int m0 = blockIdx.y * 128, n0 = blockIdx.x * 128;
    const int wm = (warp & 1) * 64, wn = (warp >> 1) * 32;

    const int lrow = tid >> 1, lch = (tid & 1) * 8;
    const __nv_bfloat16* gAh = gOh + (size_t)(m0 + lrow) * DM + lch;
    const __nv_bfloat16* gAl = gOl + (size_t)(m0 + lrow) * DM + lch;
    const __nv_bfloat16* gBh = Wh + (size_t)(n0 + lrow) * DM + lch;
    const __nv_bfloat16* gBl = Wl + (size_t)(n0 + lrow) * DM + lch;
    const int so = lrow * SAPAD + lch;

    float c[4][4][4];
    #pragma unroll
    for (int i = 0; i < 4; i++)
        #pragma unroll
        for (int j = 0; j < 4; j++)
            #pragma unroll
            for (int r = 0; r < 4; r++) c[i][j][r] = 0.0f;

    cp16(&sA[0][0][so], gAh); cp16(&sA[0][1][so], gAl);
    cp16(&sB[0][0][so], gBh); cp16(&sB[0][1][so], gBl);
    CP_COMMIT();

    const int ar = lane & 15, ac = (lane >> 4) * 8;
    const int br = lane & 7,  bc = ((lane >> 3) & 1) * 8;

    for (int kt = 0; kt < 64; kt++) {
        const int st = kt & 1;
        CP_WAIT0();
        __syncthreads();
        if (kt < 63) {
            int ko = (kt + 1) * 16;
            cp16(&sA[st ^ 1][0][so], gAh + ko); cp16(&sA[st ^ 1][1][so], gAl + ko);
            cp16(&sB[st ^ 1][0][so], gBh + ko); cp16(&sB[st ^ 1][1][so], gBl + ko);
            CP_COMMIT();
        }

        unsigned bhf[4][2], blf[4][2];
        #pragma unroll
        for (int ni = 0; ni < 4; ni++) {
            int off = (wn + ni * 8 + br) * SAPAD + bc;
            ldm_x2(bhf[ni][0], bhf[ni][1], &sB[st][0][off]);
            ldm_x2(blf[ni][0], blf[ni][1], &sB[st][1][off]);
        }
        #pragma unroll
        for (int mi = 0; mi < 4; mi++) {
            unsigned ah[4], al[4];
            int off = (wm + mi * 16 + ar) * SAPAD + ac;
            ldm_x4(ah[0], ah[1], ah[2], ah[3], &sA[st][0][off]);
            ldm_x4(al[0], al[1], al[2], al[3], &sA[st][1][off]);
            #pragma unroll
            for (int ni = 0; ni < 4; ni++) {
                mma16816(c[mi][ni], ah[0], ah[1], ah[2], ah[3], bhf[ni][0], bhf[ni][1]);
                mma16816(c[mi][ni], ah[0], ah[1], ah[2], ah[3], blf[ni][0], blf[ni][1]);
                mma16816(c[mi][ni], al[0], al[1], al[2], al[3], bhf[ni][0], bhf[ni][1]);
            }
        }
    }

    const int r0 = lane >> 2, cq = (lane & 3) * 2;
    #pragma unroll
    for (int mi = 0; mi < 4; mi++) {
        #pragma unroll
        for (int ni = 0; ni < 4; ni++) {
            int col = n0 + wn + ni * 8 + cq;
            float b0 = bo[col], b1 = bo[col + 1];
            #pragma unroll
            for (int half = 0; half < 2; half++) {
                int row = m0 + wm + mi * 16 + r0 + half * 8;
                float2 v = make_float2(c[mi][ni][half * 2 + 0] + b0,
                                       c[mi][ni][half * 2 + 1] + b1);
                *(float2*)&out[(size_t)row * DM + col] = v;
            }
        }
    }
}

// ---------------- flash attention -------------------------------------------
// S: 3-term split bf16. PV: P fp16-single x V fp16-pair (2 MMAs).
// XOR-swizzled smem (no padding): Q 2x128x64, KV 2 stages x 4 x 64x64.
// Total 98,304 B -> 2 CTAs/SM.
#define QTSZ   (128*64)              // elems per Q tile
#define KVTSZ  (64*64)               // elems per K/V tile
#define KVSTG  (4*KVTSZ)             // elems per KV stage
#define FLASH_SMEM ((2*QTSZ + 2*KVSTG) * 2)   // bytes = 98304

__global__ __launch_bounds__(256, 2) void flash()
{
    extern __shared__ __nv_bfloat16 sm[];
    __nv_bfloat16* sQh = sm;                 // [128x64] swizzled
    __nv_bfloat16* sQl = sm + QTSZ;
    __nv_bfloat16* sKV = sm + 2 * QTSZ;      // [stage][Kh,Kl,Vh,Vl][64x64]

    const int tid = threadIdx.x, lane = tid & 31, warp = tid >> 5;
    const int bh = blockIdx.y, q0 = blockIdx.x * 128;
    const size_t base = (size_t)bh * NSEQ * HD;

    // Q tiles: 2 x 1024 chunks; 8 per thread
    #pragma unroll
    for (int u = 0; u < 8; u++) {
        int id = tid + u * 256;
        int t = id >> 10, rem = id & 1023;
        int r = rem >> 3, c8 = rem & 7;
        const __nv_bfloat16* src = (t == 0) ? gQh : gQl;
        __nv_bfloat16* dst = (t == 0) ? sQh : sQl;
        cp16(&dst[swz64(r, c8)], src + base + (size_t)(q0 + r) * HD + c8 * 8);
    }
    // KV stage 0: 4 x 512 chunks; 8 per thread
    #pragma unroll
    for (int u = 0; u < 8; u++) {
        int id = tid + u * 256;
        int t = id >> 9, rem = id & 511;
        int r = rem >> 3, c8 = rem & 7;
        size_t g = base + (size_t)r * HD + c8 * 8;
        const void* src = (t == 0) ? (const void*)(gKh + g)
                        : (t == 1) ? (const void*)(gKl + g)
                        : (t == 2) ? (const void*)(gVh16 + g)
                                   : (const void*)(gVl16 + g);
        cp16(&sKV[t * KVTSZ + swz64(r, c8)], src);
    }
    CP_COMMIT();

    float o[8][4];
    #pragma unroll
    for (int i = 0; i < 8; i++)
        #pragma unroll
        for (int j = 0; j < 4; j++) o[i][j] = 0.0f;
    float mr0 = -1e30f, mr1 = -1e30f, lr0 = 0.0f, lr1 = 0.0f;

    const int ar = lane & 15;
    const int achk = lane >> 4;          // A-operand chunk half
    const int br = lane & 7;
    const int bchk = (lane >> 3) & 1;    // B-operand chunk half

    for (int kt = 0; kt < NSEQ / 64; kt++) {
        const int st = kt & 1;
        CP_WAIT0();
        __syncthreads();
        if (kt < NSEQ / 64 - 1) {
            __nv_bfloat16* d = sKV + (st ^ 1) * KVSTG;
            size_t kb = base + (size_t)(kt + 1) * 64 * HD;
            #pragma unroll
            for (int u = 0; u < 8; u++) {
                int id = tid + u * 256;
                int t = id >> 9, rem = id & 511;
                int r = rem >> 3, c8 = rem & 7;
                size_t g = kb + (size_t)r * HD + c8 * 8;
                const void* src = (t == 0) ? (const void*)(gKh + g)
                                : (t == 1) ? (const void*)(gKl + g)
                                : (t == 2) ? (const void*)(gVh16 + g)
                                           : (const void*)(gVl16 + g);
                cp16(&d[t * KVTSZ + swz64(r, c8)], src);
            }
            CP_COMMIT();
        }

        const __nv_bfloat16* Kh = sKV + st * KVSTG;
        const __nv_bfloat16* Kl = Kh + KVTSZ;
        const __nv_bfloat16* Vh = Kh + 2 * KVTSZ;
        const __nv_bfloat16* Vl = Kh + 3 * KVTSZ;

        float s[8][4];
        #pragma unroll
        for (int i = 0; i < 8; i++)
            #pragma unroll
            for (int j = 0; j < 4; j++) s[i][j] = 0.0f;

        #pragma unroll
        for (int kk = 0; kk < 4; kk++) {
            unsigned ah[4], al[4];
            int arow = warp * 16 + ar;
            int aoff = swz64(arow, kk * 2 + achk);
            ldm_x4(ah[0], ah[1], ah[2], ah[3], &sQh[aoff]);
            ldm_x4(al[0], al[1], al[2], al[3], &sQl[aoff]);
            #pragma unroll
            for (int ni = 0; ni < 8; ni++) {
                unsigned b0, b1, c0, c1;
                int krow = ni * 8 + br;
                int koff = swz64(krow, kk * 2 + bchk);
                ldm_x2(b0, b1, &Kh[koff]);
                ldm_x2(c0, c1, &Kl[koff]);
                mma16816(s[ni], ah[0], ah[1], ah[2], ah[3], b0, b1);
                mma16816(s[ni], ah[0], ah[1], ah[2], ah[3], c0, c1);
                mma16816(s[ni], al[0], al[1], al[2], al[3], b0, b1);
            }
        }

        float mx0 = -1e30f, mx1 = -1e30f;
        #pragma unroll
        for (int ni = 0; ni < 8; ni++) {
            mx0 = fmaxf(mx0, fmaxf(s[ni][0], s[ni][1]));
            mx1 = fmaxf(mx1, fmaxf(s[ni][2], s[ni][3]));
        }
        mx0 = fmaxf(mx0, __shfl_xor_sync(0xffffffffu, mx0, 1));
        mx0 = fmaxf(mx0, __shfl_xor_sync(0xffffffffu, mx0, 2));
        mx1 = fmaxf(mx1, __shfl_xor_sync(0xffffffffu, mx1, 1));
        mx1 = fmaxf(mx1, __shfl_xor_sync(0xffffffffu, mx1, 2));

        float nm0 = fmaxf(mr0, mx0), nm1 = fmaxf(mr1, mx1);
        float cr0 = __expf(mr0 - nm0), cr1 = __expf(mr1 - nm1);
        mr0 = nm0; mr1 = nm1;

        float sum0 = 0.0f, sum1 = 0.0f;
        #pragma unroll
        for (int ni = 0; ni < 8; ni++) {
            s[ni][0] = __expf(s[ni][0] - nm0);
            s[ni][1] = __expf(s[ni][1] - nm0);
            s[ni][2] = __expf(s[ni][2] - nm1);
            s[ni][3] = __expf(s[ni][3] - nm1);
            sum0 += s[ni][0] + s[ni][1];
            sum1 += s[ni][2] + s[ni][3];
        }
        sum0 += __shfl_xor_sync(0xffffffffu, sum0, 1);
        sum0 += __shfl_xor_sync(0xffffffffu, sum0, 2);
        sum1 += __shfl_xor_sync(0xffffffffu, sum1, 1);
        sum1 += __shfl_xor_sync(0xffffffffu, sum1, 2);
        lr0 = lr0 * cr0 + sum0;
        lr1 = lr1 * cr1 + sum1;
        #pragma unroll
        for (int dj = 0; dj < 8; dj++) {
            o[dj][0] *= cr0; o[dj][1] *= cr0;
            o[dj][2] *= cr1; o[dj][3] *= cr1;
        }

        // O += P(fp16) . V(fp16 hi+lo): 2 MMAs per 16x8 tile
        #pragma unroll
        for (int kk = 0; kk < 4; kk++) {
            unsigned p0 = pack_h2(s[2*kk][0],   s[2*kk][1]);
            unsigned p1 = pack_h2(s[2*kk][2],   s[2*kk][3]);
            unsigned p2 = pack_h2(s[2*kk+1][0], s[2*kk+1][1]);
            unsigned p3 = pack_h2(s[2*kk+1][2], s[2*kk+1][3]);
            int vrow = kk * 16 + ar;
            #pragma unroll
            for (int dj = 0; dj < 8; dj++) {
                unsigned vb0, vb1, vc0, vc1;
                int voff = swz64(vrow, dj);
                ldm_x2t(vb0, vb1, &Vh[voff]);
                ldm_x2t(vc0, vc1, &Vl[voff]);
                mma16816h(o[dj], p0, p1, p2, p3, vb0, vb1);
                mma16816h(o[dj], p0, p1, p2, p3, vc0, vc1);
            }
        }
    }

    const int b = bh >> 4, h = bh & 15;
    const int row0 = q0 + warp * 16 + (lane >> 2);
    const float inv0 = 1.0f / lr0, inv1 = 1.0f / lr1;
    const size_t rb = ((size_t)(b * NSEQ) + row0) * DM + h * HD;
    #pragma unroll
    for (int dj = 0; dj < 8; dj++) {
        int d = dj * 8 + (lane & 3) * 2;
        unsigned ph, pl;
        split_pack(o[dj][0] * inv0, o[dj][1] * inv0, ph, pl);
        *(unsigned*)&gOh[rb + d] = ph;
        *(unsigned*)&gOl[rb + d] = pl;
        split_pack(o[dj][2] * inv1, o[dj][3] * inv1, ph, pl);
        *(unsigned*)&gOh[rb + (size_t)8 * DM + d] = ph;
        *(unsigned*)&gOl[rb + (size_t)8 * DM + d] = pl;
    }
}

// ---------------------------------------------------------------------------
extern "C" void kernel_launch(void* const* d_in, const int* in_sizes, int n_in,
                              void* d_out, int out_size)
{
    (void)in_sizes; (void)n_in; (void)out_size;
    const float* queries = (const float*)d_in[0];
    const float* keys    = (const float*)d_in[1];
    const float* values  = (const float*)d_in[2];
    const float* Wq = (const float*)d_in[3];
    const float* bq = (const float*)d_in[4];
    const float* Wk = (const float*)d_in[5];
    const float* bk = (const float*)d_in[6];
    const float* Wv = (const float*)d_in[7];
    const float* bv = (const float*)d_in[8];
    const float* Wo = (const float*)d_in[9];
    const float* bo = (const float*)d_in[10];
    float* out = (float*)d_out;

    cudaFuncSetAttribute(flash, cudaFuncAttributeMaxDynamicSharedMemorySize,
                         FLASH_SMEM);

    // fp32 -> split bf16 (single launch)
    split_all<<<2048, 256>>>(queries, keys, values, Wq, Wk, Wv, Wo);

    // QKV projections
    gemm_qkv<<<dim3(DM / 128, MROWS / 128, 3), 256>>>(bq, bk, bv);

    // attention
    flash<<<dim3(NSEQ / 128, NB * NH), 256, FLASH_SMEM>>>();

    // output projection
    gemm_out<<<dim3(DM / 128, MROWS / 128), 256>>>(bo, out);
}

// round 6
// speedup vs baseline: 1.0386x; 1.0386x over previous
#include <cuda_runtime.h>
#include <cuda_bf16.h>
#include <cuda_fp16.h>
#include <math.h>
#include <stdint.h>

#define DM   1024
#define NSEQ 2048
#define NB   2
#define NH   16
#define HD   64
#define MROWS (NB*NSEQ)          // 4096
#define NELEM ((size_t)MROWS*DM) // 4,194,304
#define WELEM ((size_t)DM*DM)    // 1,048,576

// ---------------- scratch (__device__ globals; no allocations) -------------
__device__ __nv_bfloat16 gXh[3*NELEM];   // split inputs q,k,v
__device__ __nv_bfloat16 gXl[3*NELEM];
__device__ __nv_bfloat16 gWh[4*WELEM];   // split weights Wq,Wk,Wv,Wo
__device__ __nv_bfloat16 gWl[4*WELEM];
__device__ __nv_bfloat16 gQh[NELEM], gQl[NELEM];  // (b,h,n,d), Q pre-scaled
__device__ __nv_bfloat16 gKh[NELEM], gKl[NELEM];
__device__ __half        gVh16[NELEM], gVl16[NELEM]; // V as fp16 pair
__device__ __nv_bfloat16 gOh[NELEM], gOl[NELEM];  // attn out (b*n, h*d)

// ---------------- PTX helpers ---------------------------------------------
__device__ __forceinline__ void mma16816(float* c,
    unsigned a0, unsigned a1, unsigned a2, unsigned a3,
    unsigned b0, unsigned b1)
{
    asm volatile(
        "mma.sync.aligned.m16n8k16.row.col.f32.bf16.bf16.f32 "
        "{%0,%1,%2,%3},{%4,%5,%6,%7},{%8,%9},{%0,%1,%2,%3};"
        : "+f"(c[0]), "+f"(c[1]), "+f"(c[2]), "+f"(c[3])
        : "r"(a0), "r"(a1), "r"(a2), "r"(a3), "r"(b0), "r"(b1));
}

__device__ __forceinline__ void mma16816h(float* c,
    unsigned a0, unsigned a1, unsigned a2, unsigned a3,
    unsigned b0, unsigned b1)
{
    asm volatile(
        "mma.sync.aligned.m16n8k16.row.col.f32.f16.f16.f32 "
        "{%0,%1,%2,%3},{%4,%5,%6,%7},{%8,%9},{%0,%1,%2,%3};"
        : "+f"(c[0]), "+f"(c[1]), "+f"(c[2]), "+f"(c[3])
        : "r"(a0), "r"(a1), "r"(a2), "r"(a3), "r"(b0), "r"(b1));
}

__device__ __forceinline__ void ldm_x4(unsigned& r0, unsigned& r1,
                                       unsigned& r2, unsigned& r3,
                                       const void* p)
{
    unsigned a = (unsigned)__cvta_generic_to_shared(p);
    asm volatile("ldmatrix.sync.aligned.m8n8.x4.shared.b16 {%0,%1,%2,%3},[%4];"
                 : "=r"(r0), "=r"(r1), "=r"(r2), "=r"(r3) : "r"(a));
}

__device__ __forceinline__ void ldm_x2(unsigned& r0, unsigned& r1, const void* p)
{
    unsigned a = (unsigned)__cvta_generic_to_shared(p);
    asm volatile("ldmatrix.sync.aligned.m8n8.x2.shared.b16 {%0,%1},[%2];"
                 : "=r"(r0), "=r"(r1) : "r"(a));
}

__device__ __forceinline__ void ldm_x2t(unsigned& r0, unsigned& r1, const void* p)
{
    unsigned a = (unsigned)__cvta_generic_to_shared(p);
    asm volatile("ldmatrix.sync.aligned.m8n8.x2.trans.shared.b16 {%0,%1},[%2];"
                 : "=r"(r0), "=r"(r1) : "r"(a));
}

__device__ __forceinline__ void cp16(void* dst, const void* src)
{
    unsigned d = (unsigned)__cvta_generic_to_shared(dst);
    asm volatile("cp.async.cg.shared.global [%0], [%1], 16;" :: "r"(d), "l"(src));
}
#define CP_COMMIT() asm volatile("cp.async.commit_group;")
#define CP_WAIT0()  asm volatile("cp.async.wait_group 0;")

// split fp32 pair -> packed bf16x2 hi + bf16x2 lo
__device__ __forceinline__ void split_pack(float x, float y,
                                           unsigned& h, unsigned& l)
{
    __nv_bfloat16 hx = __float2bfloat16(x);
    __nv_bfloat16 hy = __float2bfloat16(y);
    float rx = x - __bfloat162float(hx);
    float ry = y - __bfloat162float(hy);
    __nv_bfloat16 lx = __float2bfloat16(rx);
    __nv_bfloat16 ly = __float2bfloat16(ry);
    h = ((unsigned)__bfloat16_as_ushort(hy) << 16) | __bfloat16_as_ushort(hx);
    l = ((unsigned)__bfloat16_as_ushort(ly) << 16) | __bfloat16_as_ushort(lx);
}

// split fp32 pair -> packed fp16x2 hi + fp16x2 lo
__device__ __forceinline__ void split_pack_h(float x, float y,
                                             unsigned& h, unsigned& l)
{
    __half hx = __float2half_rn(x);
    __half hy = __float2half_rn(y);
    float rx = x - __half2float(hx);
    float ry = y - __half2float(hy);
    __half2 hp = __halves2half2(hx, hy);
    __half2 lp = __halves2half2(__float2half_rn(rx), __float2half_rn(ry));
    h = *(unsigned*)&hp;
    l = *(unsigned*)&lp;
}

__device__ __forceinline__ unsigned pack_h2(float x, float y)
{
    __half2 p = __floats2half2_rn(x, y);
    return *(unsigned*)&p;
}

// 16B-chunk XOR swizzle for 64-col bf16 tiles (row*64 elems + chunk^row&7)
__device__ __forceinline__ int swz64(int r, int c8)
{
    return r * 64 + ((c8 ^ (r & 7)) * 8);
}

// ---------------- merged fp32 -> split bf16 conversion (single launch) -----
#define NF4_IN (NELEM >> 2)   // 2^20 float4 per input tensor
#define NF4_W  (WELEM >> 2)   // 2^18 float4 per weight tensor
#define NF4_TOT (3*NF4_IN + 4*NF4_W)

__global__ void split_all(const float* __restrict__ q, const float* __restrict__ k,
                          const float* __restrict__ v, const float* __restrict__ wq,
                          const float* __restrict__ wk, const float* __restrict__ wv,
                          const float* __restrict__ wo)
{
    for (size_t i = blockIdx.x * blockDim.x + threadIdx.x; i < NF4_TOT;
         i += (size_t)gridDim.x * blockDim.x) {
        const float* src;
        __nv_bfloat16 *h, *l;
        size_t off;
        if (i < 3*NF4_IN) {
            int slot = (int)(i >> 20);
            off = i & (NF4_IN - 1);
            src = (slot == 0) ? q : (slot == 1) ? k : v;
            h = gXh + (size_t)slot * NELEM;
            l = gXl + (size_t)slot * NELEM;
        } else {
            size_t j = i - 3*NF4_IN;
            int slot = (int)(j >> 18);
            off = j & (NF4_W - 1);
            src = (slot == 0) ? wq : (slot == 1) ? wk : (slot == 2) ? wv : wo;
            h = gWh + (size_t)slot * WELEM;
            l = gWl + (size_t)slot * WELEM;
        }
        float4 val = ((const float4*)src)[off];
        unsigned h0, l0, h1, l1;
        split_pack(val.x, val.y, h0, l0);
        split_pack(val.z, val.w, h1, l1);
        ((uint2*)h)[off] = make_uint2(h0, h1);
        ((uint2*)l)[off] = make_uint2(l0, l1);
    }
}

// ---------------- GEMM mainloop body (term-major MMA order) ----------------
// Computes the 12 MMAs for an mi-pair with same-accumulator distance 8.
#define GEMM_PAIR_BODY(mp)                                                    \
    {                                                                         \
        unsigned ah[2][4], al[2][4];                                          \
        _Pragma("unroll")                                                     \
        for (int q = 0; q < 2; q++) {                                         \
            int off = (wm + ((mp)*2 + q) * 16 + ar) * SAPAD + ac;             \
            ldm_x4(ah[q][0], ah[q][1], ah[q][2], ah[q][3], &sA[st][0][off]);  \
            ldm_x4(al[q][0], al[q][1], al[q][2], al[q][3], &sA[st][1][off]);  \
        }                                                                     \
        _Pragma("unroll")                                                     \
        for (int q = 0; q < 2; q++)                                           \
            _Pragma("unroll")                                                 \
            for (int ni = 0; ni < 4; ni++)                                    \
                mma16816(c[(mp)*2 + q][ni], ah[q][0], ah[q][1], ah[q][2],     \
                         ah[q][3], bhf[ni][0], bhf[ni][1]);                   \
        _Pragma("unroll")                                                     \
        for (int q = 0; q < 2; q++)                                           \
            _Pragma("unroll")                                                 \
            for (int ni = 0; ni < 4; ni++)                                    \
                mma16816(c[(mp)*2 + q][ni], ah[q][0], ah[q][1], ah[q][2],     \
                         ah[q][3], blf[ni][0], blf[ni][1]);                   \
        _Pragma("unroll")                                                     \
        for (int q = 0; q < 2; q++)                                           \
            _Pragma("unroll")                                                 \
            for (int ni = 0; ni < 4; ni++)                                    \
                mma16816(c[(mp)*2 + q][ni], al[q][0], al[q][1], al[q][2],     \
                         al[q][3], bhf[ni][0], bhf[ni][1]);                   \
    }

// ---------------- QKV projection GEMM (split bf16 tensor cores) ------------
#define SAPAD 24

__global__ __launch_bounds__(256, 2) void gemm_qkv(
    const float* __restrict__ bq, const float* __restrict__ bk,
    const float* __restrict__ bv)
{
    __shared__ __nv_bfloat16 sA[2][2][128*SAPAD];
    __shared__ __nv_bfloat16 sB[2][2][128*SAPAD];

    const int z = blockIdx.z;
    const __nv_bfloat16* Xh = gXh + (size_t)z * NELEM;
    const __nv_bfloat16* Xl = gXl + (size_t)z * NELEM;
    const __nv_bfloat16* Wh = gWh + (size_t)z * WELEM;
    const __nv_bfloat16* Wl = gWl + (size_t)z * WELEM;
    const float* bias = (z == 0) ? bq : (z == 1) ? bk : bv;
    const float scale = (z == 0) ? 0.125f : 1.0f;

    const int tid = threadIdx.x, lane = tid & 31, warp = tid >> 5;
    const int m0 = blockIdx.y * 128, n0 = blockIdx.x * 128;
    const int wm = (warp & 1) * 64, wn = (warp >> 1) * 32;

    const int lrow = tid >> 1, lch = (tid & 1) * 8;
    const __nv_bfloat16* gAh = Xh + (size_t)(m0 + lrow) * DM + lch;
    const __nv_bfloat16* gAl = Xl + (size_t)(m0 + lrow) * DM + lch;
    const __nv_bfloat16* gBh = Wh + (size_t)(n0 + lrow) * DM + lch;
    const __nv_bfloat16* gBl = Wl + (size_t)(n0 + lrow) * DM + lch;
    const int so = lrow * SAPAD + lch;

    float c[4][4][4];
    #pragma unroll
    for (int i = 0; i < 4; i++)
        #pragma unroll
        for (int j = 0; j < 4; j++)
            #pragma unroll
            for (int r = 0; r < 4; r++) c[i][j][r] = 0.0f;

    cp16(&sA[0][0][so], gAh); cp16(&sA[0][1][so], gAl);
    cp16(&sB[0][0][so], gBh); cp16(&sB[0][1][so], gBl);
    CP_COMMIT();

    const int ar = lane & 15, ac = (lane >> 4) * 8;
    const int br = lane & 7,  bc = ((lane >> 3) & 1) * 8;

    for (int kt = 0; kt < 64; kt++) {
        const int st = kt & 1;
        CP_WAIT0();
        __syncthreads();
        if (kt < 63) {
            int ko = (kt + 1) * 16;
            cp16(&sA[st ^ 1][0][so], gAh + ko); cp16(&sA[st ^ 1][1][so], gAl + ko);
            cp16(&sB[st ^ 1][0][so], gBh + ko); cp16(&sB[st ^ 1][1][so], gBl + ko);
            CP_COMMIT();
        }

        unsigned bhf[4][2], blf[4][2];
        #pragma unroll
        for (int ni = 0; ni < 4; ni++) {
            int off = (wn + ni * 8 + br) * SAPAD + bc;
            ldm_x2(bhf[ni][0], bhf[ni][1], &sB[st][0][off]);
            ldm_x2(blf[ni][0], blf[ni][1], &sB[st][1][off]);
        }
        GEMM_PAIR_BODY(0)
        GEMM_PAIR_BODY(1)
    }

    // epilogue: + bias, * scale(Q), split, scatter to (b,h,n,d)
    const int r0 = lane >> 2, cq = (lane & 3) * 2;
    #pragma unroll
    for (int mi = 0; mi < 4; mi++) {
        #pragma unroll
        for (int ni = 0; ni < 4; ni++) {
            int col = n0 + wn + ni * 8 + cq;
            float b0 = bias[col], b1 = bias[col + 1];
            int hh = col >> 6, d = col & 63;
            #pragma unroll
            for (int half = 0; half < 2; half++) {
                int row = m0 + wm + mi * 16 + r0 + half * 8;
                float v0 = (c[mi][ni][half * 2 + 0] + b0) * scale;
                float v1 = (c[mi][ni][half * 2 + 1] + b1) * scale;
                int bb = row >> 11, n = row & (NSEQ - 1);
                size_t idx = (((size_t)(bb * NH + hh)) * NSEQ + n) * HD + d;
                unsigned ph, pl;
                if (z == 2) {
                    split_pack_h(v0, v1, ph, pl);
                    *(unsigned*)&gVh16[idx] = ph;
                    *(unsigned*)&gVl16[idx] = pl;
                } else {
                    split_pack(v0, v1, ph, pl);
                    if (z == 0) { *(unsigned*)&gQh[idx] = ph; *(unsigned*)&gQl[idx] = pl; }
                    else        { *(unsigned*)&gKh[idx] = ph; *(unsigned*)&gKl[idx] = pl; }
                }
            }
        }
    }
}

// ---------------- output projection GEMM (split bf16, 3-term) --------------
__global__ __launch_bounds__(256, 2) void gemm_out(
    const float* __restrict__ bo, float* __restrict__ out)
{
    __shared__ __nv_bfloat16 sA[2][2][128*SAPAD];
    __shared__ __nv_bfloat16 sB[2][2][128*SAPAD];

    const __nv_bfloat16* Wh = gWh + 3 * WELEM;
    const __nv_bfloat16* Wl = gWl + 3 * WELEM;

    const int tid = threadIdx.x, lane = tid & 31, warp = tid >> 5;
    const int m0 = blockIdx.y * 128, n0 = blockIdx.x * 128;
    const int wm = (warp & 1) * 64, wn = (warp >> 1) * 32;

    const int lrow = tid >> 1, lch = (tid & 1) * 8;
    const __nv_bfloat16* gAh = gOh + (size_t)(m0 + lrow) * DM + lch;
    const __nv_bfloat16* gAl = gOl + (size_t)(m0 + lrow) * DM + lch;
    const __nv_bfloat16* gBh = Wh + (size_t)(n0 + lrow) * DM + lch;
    const __nv_bfloat16* gBl = Wl + (size_t)(n0 + lrow) * DM + lch;
    const int so = lrow * SAPAD + lch;

    float c[4][4][4];
    #pragma unroll
    for (int i = 0; i < 4; i++)
        #pragma unroll
        for (int j = 0; j < 4; j++)
            #pragma unroll
            for (int r = 0; r < 4; r++) c[i][j][r] = 0.0f;

    cp16(&sA[0][0][so], gAh); cp16(&sA[0][1][so], gAl);
    cp16(&sB[0][0][so], gBh); cp16(&sB[0][1][so], gBl);
    CP_COMMIT();

    const int ar = lane & 15, ac = (lane >> 4) * 8;
    const int br = lane & 7,  bc = ((lane >> 3) & 1) * 8;

    for (int kt = 0; kt < 64; kt++) {
        const int st = kt & 1;
        CP_WAIT0();
        __syncthreads();
        if (kt < 63) {
            int ko = (kt + 1) * 16;
            cp16(&sA[st ^ 1][0][so], gAh + ko); cp16(&sA[st ^ 1][1][so], gAl + ko);
            cp16(&sB[st ^ 1][0][so], gBh + ko); cp16(&sB[st ^ 1][1][so], gBl + ko);
            CP_COMMIT();
        }

        unsigned bhf[4][2], blf[4][2];
        #pragma unroll
        for (int ni = 0; ni < 4; ni++) {
            int off = (wn + ni * 8 + br) * SAPAD + bc;
            ldm_x2(bhf[ni][0], bhf[ni][1], &sB[st][0][off]);
            ldm_x2(blf[ni][0], blf[ni][1], &sB[st][1][off]);
        }
        GEMM_PAIR_BODY(0)
        GEMM_PAIR_BODY(1)
    }

    const int r0 = lane >> 2, cq = (lane & 3) * 2;
    #pragma unroll
    for (int mi = 0; mi < 4; mi++) {
        #pragma unroll
        for (int ni = 0; ni < 4; ni++) {
            int col = n0 + wn + ni * 8 + cq;
            float b0 = bo[col], b1 = bo[col + 1];
            #pragma unroll
            for (int half = 0; half < 2; half++) {
                int row = m0 + wm + mi * 16 + r0 + half * 8;
                float2 v = make_float2(c[mi][ni][half * 2 + 0] + b0,
                                       c[mi][ni][half * 2 + 1] + b1);
                *(float2*)&out[(size_t)row * DM + col] = v;
            }
        }
    }
}

// ---------------- flash attention -------------------------------------------
// S: 3-term split bf16. PV: P fp16-single x V fp16-pair (2 MMAs).
// XOR-swizzled smem: Q 2x128x64, KV 2 stages x 4 x 64x64. 98,304 B -> 2 CTAs/SM.
#define QTSZ   (128*64)              // elems per Q tile
#define KVTSZ  (64*64)               // elems per K/V tile
#define KVSTG  (4*KVTSZ)             // elems per KV stage
#define FLASH_SMEM ((2*QTSZ + 2*KVSTG) * 2)   // bytes = 98304

__global__ __launch_bounds__(256, 2) void flash()
{
    extern __shared__ __nv_bfloat16 sm[];
    __nv_bfloat16* sQh = sm;                 // [128x64] swizzled
    __nv_bfloat16* sQl = sm + QTSZ;
    __nv_bfloat16* sKV = sm + 2 * QTSZ;      // [stage][Kh,Kl,Vh,Vl][64x64]

    const int tid = threadIdx.x, lane = tid & 31, warp = tid >> 5;
    const int bh = blockIdx.y, q0 = blockIdx.x * 128;
    const size_t base = (size_t)bh * NSEQ * HD;

    // Q tiles: 2 x 1024 chunks; 8 per thread
    #pragma unroll
    for (int u = 0; u < 8; u++) {
        int id = tid + u * 256;
        int t = id >> 10, rem = id & 1023;
        int r = rem >> 3, c8 = rem & 7;
        const __nv_bfloat16* src = (t == 0) ? gQh : gQl;
        __nv_bfloat16* dst = (t == 0) ? sQh : sQl;
        cp16(&dst[swz64(r, c8)], src + base + (size_t)(q0 + r) * HD + c8 * 8);
    }
    // KV stage 0: 4 x 512 chunks; 8 per thread
    #pragma unroll
    for (int u = 0; u < 8; u++) {
        int id = tid + u * 256;
        int t = id >> 9, rem = id & 511;
        int r = rem >> 3, c8 = rem & 7;
        size_t g = base + (size_t)r * HD + c8 * 8;
        const void* src = (t == 0) ? (const void*)(gKh + g)
                        : (t == 1) ? (const void*)(gKl + g)
                        : (t == 2) ? (const void*)(gVh16 + g)
                                   : (const void*)(gVl16 + g);
        cp16(&sKV[t * KVTSZ + swz64(r, c8)], src);
    }
    CP_COMMIT();

    float o[8][4];
    #pragma unroll
    for (int i = 0; i < 8; i++)
        #pragma unroll
        for (int j = 0; j < 4; j++) o[i][j] = 0.0f;
    float mr0 = -1e30f, mr1 = -1e30f, lr0 = 0.0f, lr1 = 0.0f;

    const int ar = lane & 15;
    const int achk = lane >> 4;          // A-operand chunk half
    const int br = lane & 7;
    const int bchk = (lane >> 3) & 1;    // B-operand chunk half

    for (int kt = 0; kt < NSEQ / 64; kt++) {
        const int st = kt & 1;
        CP_WAIT0();
        __syncthreads();
        if (kt < NSEQ / 64 - 1) {
            __nv_bfloat16* d = sKV + (st ^ 1) * KVSTG;
            size_t kb = base + (size_t)(kt + 1) * 64 * HD;
            #pragma unroll
            for (int u = 0; u < 8; u++) {
                int id = tid + u * 256;
                int t = id >> 9, rem = id & 511;
                int r = rem >> 3, c8 = rem & 7;
                size_t g = kb + (size_t)r * HD + c8 * 8;
                const void* src = (t == 0) ? (const void*)(gKh + g)
                                : (t == 1) ? (const void*)(gKl + g)
                                : (t == 2) ? (const void*)(gVh16 + g)
                                           : (const void*)(gVl16 + g);
                cp16(&d[t * KVTSZ + swz64(r, c8)], src);
            }
            CP_COMMIT();
        }

        const __nv_bfloat16* Kh = sKV + st * KVSTG;
        const __nv_bfloat16* Kl = Kh + KVTSZ;
        const __nv_bfloat16* Vh = Kh + 2 * KVTSZ;
        const __nv_bfloat16* Vl = Kh + 3 * KVTSZ;

        float s[8][4];
        #pragma unroll
        for (int i = 0; i < 8; i++)
            #pragma unroll
            for (int j = 0; j < 4; j++) s[i][j] = 0.0f;

        // S = Q.K^T — term-major over ni-quads (same-acc distance 4)
        #pragma unroll
        for (int kk = 0; kk < 4; kk++) {
            unsigned ah[4], al[4];
            int arow = warp * 16 + ar;
            int aoff = swz64(arow, kk * 2 + achk);
            ldm_x4(ah[0], ah[1], ah[2], ah[3], &sQh[aoff]);
            ldm_x4(al[0], al[1], al[2], al[3], &sQl[aoff]);
            #pragma unroll
            for (int nh = 0; nh < 2; nh++) {
                unsigned kb4[4][2], kc4[4][2];
                #pragma unroll
                for (int nq = 0; nq < 4; nq++) {
                    int krow = (nh * 4 + nq) * 8 + br;
                    int koff = swz64(krow, kk * 2 + bchk);
                    ldm_x2(kb4[nq][0], kb4[nq][1], &Kh[koff]);
                    ldm_x2(kc4[nq][0], kc4[nq][1], &Kl[koff]);
                }
                #pragma unroll
                for (int nq = 0; nq < 4; nq++)
                    mma16816(s[nh * 4 + nq], ah[0], ah[1], ah[2], ah[3],
                             kb4[nq][0], kb4[nq][1]);
                #pragma unroll
                for (int nq = 0; nq < 4; nq++)
                    mma16816(s[nh * 4 + nq], ah[0], ah[1], ah[2], ah[3],
                             kc4[nq][0], kc4[nq][1]);
                #pragma unroll
                for (int nq = 0; nq < 4; nq++)
                    mma16816(s[nh * 4 + nq], al[0], al[1], al[2], al[3],
                             kb4[nq][0], kb4[nq][1]);
            }
        }

        float mx0 = -1e30f, mx1 = -1e30f;
        #pragma unroll
        for (int ni = 0; ni < 8; ni++) {
            mx0 = fmaxf(mx0, fmaxf(s[ni][0], s[ni][1]));
            mx1 = fmaxf(mx1, fmaxf(s[ni][2], s[ni][3]));
        }
        mx0 = fmaxf(mx0, __shfl_xor_sync(0xffffffffu, mx0, 1));
        mx0 = fmaxf(mx0, __shfl_xor_sync(0xffffffffu, mx0, 2));
        mx1 = fmaxf(mx1, __shfl_xor_sync(0xffffffffu, mx1, 1));
        mx1 = fmaxf(mx1, __shfl_xor_sync(0xffffffffu, mx1, 2));

        float nm0 = fmaxf(mr0, mx0), nm1 = fmaxf(mr1, mx1);
        float cr0 = __expf(mr0 - nm0), cr1 = __expf(mr1 - nm1);
        mr0 = nm0; mr1 = nm1;

        float sum0 = 0.0f, sum1 = 0.0f;
        #pragma unroll
        for (int ni = 0; ni < 8; ni++) {
            s[ni][0] = __expf(s[ni][0] - nm0);
            s[ni][1] = __expf(s[ni][1] - nm0);
            s[ni][2] = __expf(s[ni][2] - nm1);
            s[ni][3] = __expf(s[ni][3] - nm1);
            sum0 += s[ni][0] + s[ni][1];
            sum1 += s[ni][2] + s[ni][3];
        }
        sum0 += __shfl_xor_sync(0xffffffffu, sum0, 1);
        sum0 += __shfl_xor_sync(0xffffffffu, sum0, 2);
        sum1 += __shfl_xor_sync(0xffffffffu, sum1, 1);
        sum1 += __shfl_xor_sync(0xffffffffu, sum1, 2);
        lr0 = lr0 * cr0 + sum0;
        lr1 = lr1 * cr1 + sum1;
        #pragma unroll
        for (int dj = 0; dj < 8; dj++) {
            o[dj][0] *= cr0; o[dj][1] *= cr0;
            o[dj][2] *= cr1; o[dj][3] *= cr1;
        }

        // O += P(fp16) . V(fp16 hi+lo) — term-major over dj-quads (distance 4)
        #pragma unroll
        for (int kk = 0; kk < 4; kk++) {
            unsigned p0 = pack_h2(s[2*kk][0],   s[2*kk][1]);
            unsigned p1 = pack_h2(s[2*kk][2],   s[2*kk][3]);
            unsigned p2 = pack_h2(s[2*kk+1][0], s[2*kk+1][1]);
            unsigned p3 = pack_h2(s[2*kk+1][2], s[2*kk+1][3]);
            int vrow = kk * 16 + ar;
            #pragma unroll
            for (int dh = 0; dh < 2; dh++) {
                unsigned vb4[4][2], vc4[4][2];
                #pragma unroll
                for (int dq = 0; dq < 4; dq++) {
                    int voff = swz64(vrow, dh * 4 + dq);
                    ldm_x2t(vb4[dq][0], vb4[dq][1], &Vh[voff]);
                    ldm_x2t(vc4[dq][0], vc4[dq][1], &Vl[voff]);
                }
                #pragma unroll
                for (int dq = 0; dq < 4; dq++)
                    mma16816h(o[dh * 4 + dq], p0, p1, p2, p3,
                              vb4[dq][0], vb4[dq][1]);
                #pragma unroll
                for (int dq = 0; dq < 4; dq++)
                    mma16816h(o[dh * 4 + dq], p0, p1, p2, p3,
                              vc4[dq][0], vc4[dq][1]);
            }
        }
    }

    const int b = bh >> 4, h = bh & 15;
    const int row0 = q0 + warp * 16 + (lane >> 2);
    const float inv0 = 1.0f / lr0, inv1 = 1.0f / lr1;
    const size_t rb = ((size_t)(b * NSEQ) + row0) * DM + h * HD;
    #pragma unroll
    for (int dj = 0; dj < 8; dj++) {
        int d = dj * 8 + (lane & 3) * 2;
        unsigned ph, pl;
        split_pack(o[dj][0] * inv0, o[dj][1] * inv0, ph, pl);
        *(unsigned*)&gOh[rb + d] = ph;
        *(unsigned*)&gOl[rb + d] = pl;
        split_pack(o[dj][2] * inv1, o[dj][3] * inv1, ph, pl);
        *(unsigned*)&gOh[rb + (size_t)8 * DM + d] = ph;
        *(unsigned*)&gOl[rb + (size_t)8 * DM + d] = pl;
    }
}

// ---------------------------------------------------------------------------
extern "C" void kernel_launch(void* const* d_in, const int* in_sizes, int n_in,
                              void* d_out, int out_size)
{
    (void)in_sizes; (void)n_in; (void)out_size;
    const float* queries = (const float*)d_in[0];
    const float* keys    = (const float*)d_in[1];
    const float* values  = (const float*)d_in[2];
    const float* Wq = (const float*)d_in[3];
    const float* bq = (const float*)d_in[4];
    const float* Wk = (const float*)d_in[5];
    const float* bk = (const float*)d_in[6];
    const float* Wv = (const float*)d_in[7];
    const float* bv = (const float*)d_in[8];
    const float* Wo = (const float*)d_in[9];
    const float* bo = (const float*)d_in[10];
    float* out = (float*)d_out;

    cudaFuncSetAttribute(flash, cudaFuncAttributeMaxDynamicSharedMemorySize,
                         FLASH_SMEM);

    // fp32 -> split bf16 (single launch)
    split_all<<<2048, 256>>>(queries, keys, values, Wq, Wk, Wv, Wo);

    // QKV projections
    gemm_qkv<<<dim3(DM / 128, MROWS / 128, 3), 256>>>(bq, bk, bv);

    // attention
    flash<<<dim3(NSEQ / 128, NB * NH), 256, FLASH_SMEM>>>();

    // output projection
    gemm_out<<<dim3(DM / 128, MROWS / 128), 256>>>(bo, out);
}

// round 7
// speedup vs baseline: 1.3529x; 1.3027x over previous
#include <cuda_runtime.h>
#include <cuda_bf16.h>
#include <cuda_fp16.h>
#include <math.h>
#include <stdint.h>

#define DM   1024
#define NSEQ 2048
#define NB   2
#define NH   16
#define HD   64
#define MROWS (NB*NSEQ)          // 4096
#define NELEM ((size_t)MROWS*DM) // 4,194,304
#define WELEM ((size_t)DM*DM)    // 1,048,576

// ---------------- scratch (__device__ globals; no allocations) -------------
__device__ __half gXh[3*NELEM], gXl[3*NELEM]; // split inputs q,k,v (fp16 pair)
__device__ __half gW[4*WELEM];                // weights single fp16
__device__ __half gQh[NELEM], gQl[NELEM];     // (b,h,n,d), Q pre-scaled, pair
__device__ __half gK[NELEM];                  // K single fp16
__device__ __half gVh16[NELEM], gVl16[NELEM]; // V fp16 pair
__device__ __half gOh[NELEM], gOl[NELEM];     // attn out (b*n, h*d), pair

// ---------------- PTX helpers ---------------------------------------------
__device__ __forceinline__ void mma16816h(float* c,
    unsigned a0, unsigned a1, unsigned a2, unsigned a3,
    unsigned b0, unsigned b1)
{
    asm volatile(
        "mma.sync.aligned.m16n8k16.row.col.f32.f16.f16.f32 "
        "{%0,%1,%2,%3},{%4,%5,%6,%7},{%8,%9},{%0,%1,%2,%3};"
        : "+f"(c[0]), "+f"(c[1]), "+f"(c[2]), "+f"(c[3])
        : "r"(a0), "r"(a1), "r"(a2), "r"(a3), "r"(b0), "r"(b1));
}

__device__ __forceinline__ void ldm_x4(unsigned& r0, unsigned& r1,
                                       unsigned& r2, unsigned& r3,
                                       const void* p)
{
    unsigned a = (unsigned)__cvta_generic_to_shared(p);
    asm volatile("ldmatrix.sync.aligned.m8n8.x4.shared.b16 {%0,%1,%2,%3},[%4];"
                 : "=r"(r0), "=r"(r1), "=r"(r2), "=r"(r3) : "r"(a));
}

__device__ __forceinline__ void ldm_x2(unsigned& r0, unsigned& r1, const void* p)
{
    unsigned a = (unsigned)__cvta_generic_to_shared(p);
    asm volatile("ldmatrix.sync.aligned.m8n8.x2.shared.b16 {%0,%1},[%2];"
                 : "=r"(r0), "=r"(r1) : "r"(a));
}

__device__ __forceinline__ void ldm_x2t(unsigned& r0, unsigned& r1, const void* p)
{
    unsigned a = (unsigned)__cvta_generic_to_shared(p);
    asm volatile("ldmatrix.sync.aligned.m8n8.x2.trans.shared.b16 {%0,%1},[%2];"
                 : "=r"(r0), "=r"(r1) : "r"(a));
}

__device__ __forceinline__ void cp16(void* dst, const void* src)
{
    unsigned d = (unsigned)__cvta_generic_to_shared(dst);
    asm volatile("cp.async.cg.shared.global [%0], [%1], 16;" :: "r"(d), "l"(src));
}
#define CP_COMMIT() asm volatile("cp.async.commit_group;")
#define CP_WAIT0()  asm volatile("cp.async.wait_group 0;")

// split fp32 pair -> packed fp16x2 hi + fp16x2 lo
__device__ __forceinline__ void split_pack_h(float x, float y,
                                             unsigned& h, unsigned& l)
{
    __half hx = __float2half_rn(x);
    __half hy = __float2half_rn(y);
    float rx = x - __half2float(hx);
    float ry = y - __half2float(hy);
    __half2 hp = __halves2half2(hx, hy);
    __half2 lp = __halves2half2(__float2half_rn(rx), __float2half_rn(ry));
    h = *(unsigned*)&hp;
    l = *(unsigned*)&lp;
}

__device__ __forceinline__ unsigned pack_h2(float x, float y)
{
    __half2 p = __floats2half2_rn(x, y);
    return *(unsigned*)&p;
}

// 16B-chunk XOR swizzle for 64-col fp16 tiles (row*64 elems + chunk^row&7)
__device__ __forceinline__ int swz64(int r, int c8)
{
    return r * 64 + ((c8 ^ (r & 7)) * 8);
}

// ---------------- merged fp32 -> fp16 conversion (single launch) -----------
#define NF4_IN (NELEM >> 2)   // 2^20 float4 per input tensor
#define NF4_W  (WELEM >> 2)   // 2^18 float4 per weight tensor
#define NF4_TOT (3*NF4_IN + 4*NF4_W)

__global__ void split_all(const float* __restrict__ q, const float* __restrict__ k,
                          const float* __restrict__ v, const float* __restrict__ wq,
                          const float* __restrict__ wk, const float* __restrict__ wv,
                          const float* __restrict__ wo)
{
    for (size_t i = blockIdx.x * blockDim.x + threadIdx.x; i < NF4_TOT;
         i += (size_t)gridDim.x * blockDim.x) {
        if (i < 3*NF4_IN) {
            int slot = (int)(i >> 20);
            size_t off = i & (NF4_IN - 1);
            const float* src = (slot == 0) ? q : (slot == 1) ? k : v;
            __half* h = gXh + (size_t)slot * NELEM;
            __half* l = gXl + (size_t)slot * NELEM;
            float4 val = ((const float4*)src)[off];
            unsigned h0, l0, h1, l1;
            split_pack_h(val.x, val.y, h0, l0);
            split_pack_h(val.z, val.w, h1, l1);
            ((uint2*)h)[off] = make_uint2(h0, h1);
            ((uint2*)l)[off] = make_uint2(l0, l1);
        } else {
            size_t j = i - 3*NF4_IN;
            int slot = (int)(j >> 18);
            size_t off = j & (NF4_W - 1);
            const float* src = (slot == 0) ? wq : (slot == 1) ? wk
                             : (slot == 2) ? wv : wo;
            __half* h = gW + (size_t)slot * WELEM;
            float4 val = ((const float4*)src)[off];
            ((uint2*)h)[off] = make_uint2(pack_h2(val.x, val.y),
                                          pack_h2(val.z, val.w));
        }
    }
}

// ---------------- GEMM mainloop body (2-term, term-major order) ------------
#define GEMM_PAIR_BODY(mp)                                                    \
    {                                                                         \
        unsigned ah[2][4], al[2][4];                                          \
        _Pragma("unroll")                                                     \
        for (int q = 0; q < 2; q++) {                                         \
            int off = (wm + ((mp)*2 + q) * 16 + ar) * SAPAD + ac;             \
            ldm_x4(ah[q][0], ah[q][1], ah[q][2], ah[q][3], &sA[st][0][off]);  \
            ldm_x4(al[q][0], al[q][1], al[q][2], al[q][3], &sA[st][1][off]);  \
        }                                                                     \
        _Pragma("unroll")                                                     \
        for (int q = 0; q < 2; q++)                                           \
            _Pragma("unroll")                                                 \
            for (int ni = 0; ni < 4; ni++)                                    \
                mma16816h(c[(mp)*2 + q][ni], ah[q][0], ah[q][1], ah[q][2],    \
                          ah[q][3], bf[ni][0], bf[ni][1]);                    \
        _Pragma("unroll")                                                     \
        for (int q = 0; q < 2; q++)                                           \
            _Pragma("unroll")                                                 \
            for (int ni = 0; ni < 4; ni++)                                    \
                mma16816h(c[(mp)*2 + q][ni], al[q][0], al[q][1], al[q][2],    \
                          al[q][3], bf[ni][0], bf[ni][1]);                    \
    }

// ---------------- QKV projection GEMM (2-term fp16 tensor cores) -----------
#define SAPAD 24

__global__ __launch_bounds__(256, 2) void gemm_qkv(
    const float* __restrict__ bq, const float* __restrict__ bk,
    const float* __restrict__ bv)
{
    __shared__ __half sA[2][2][128*SAPAD];
    __shared__ __half sB[2][128*SAPAD];

    const int z = blockIdx.z;
    const __half* Xh = gXh + (size_t)z * NELEM;
    const __half* Xl = gXl + (size_t)z * NELEM;
    const __half* Wp = gW + (size_t)z * WELEM;
    const float* bias = (z == 0) ? bq : (z == 1) ? bk : bv;
    const float scale = (z == 0) ? 0.125f : 1.0f;

    const int tid = threadIdx.x, lane = tid & 31, warp = tid >> 5;
    const int m0 = blockIdx.y * 128, n0 = blockIdx.x * 128;
    const int wm = (warp & 1) * 64, wn = (warp >> 1) * 32;

    const int lrow = tid >> 1, lch = (tid & 1) * 8;
    const __half* gAh = Xh + (size_t)(m0 + lrow) * DM + lch;
    const __half* gAl = Xl + (size_t)(m0 + lrow) * DM + lch;
    const __half* gB  = Wp + (size_t)(n0 + lrow) * DM + lch;
    const int so = lrow * SAPAD + lch;

    float c[4][4][4];
    #pragma unroll
    for (int i = 0; i < 4; i++)
        #pragma unroll
        for (int j = 0; j < 4; j++)
            #pragma unroll
            for (int r = 0; r < 4; r++) c[i][j][r] = 0.0f;

    cp16(&sA[0][0][so], gAh); cp16(&sA[0][1][so], gAl);
    cp16(&sB[0][so], gB);
    CP_COMMIT();

    const int ar = lane & 15, ac = (lane >> 4) * 8;
    const int br = lane & 7,  bc = ((lane >> 3) & 1) * 8;

    for (int kt = 0; kt < 64; kt++) {
        const int st = kt & 1;
        CP_WAIT0();
        __syncthreads();
        if (kt < 63) {
            int ko = (kt + 1) * 16;
            cp16(&sA[st ^ 1][0][so], gAh + ko); cp16(&sA[st ^ 1][1][so], gAl + ko);
            cp16(&sB[st ^ 1][so], gB + ko);
            CP_COMMIT();
        }

        unsigned bf[4][2];
        #pragma unroll
        for (int ni = 0; ni < 4; ni++) {
            int off = (wn + ni * 8 + br) * SAPAD + bc;
            ldm_x2(bf[ni][0], bf[ni][1], &sB[st][off]);
        }
        GEMM_PAIR_BODY(0)
        GEMM_PAIR_BODY(1)
    }

    // epilogue: + bias, * scale(Q), convert, scatter to (b,h,n,d)
    const int r0 = lane >> 2, cq = (lane & 3) * 2;
    #pragma unroll
    for (int mi = 0; mi < 4; mi++) {
        #pragma unroll
        for (int ni = 0; ni < 4; ni++) {
            int col = n0 + wn + ni * 8 + cq;
            float b0 = bias[col], b1 = bias[col + 1];
            int hh = col >> 6, d = col & 63;
            #pragma unroll
            for (int half = 0; half < 2; half++) {
                int row = m0 + wm + mi * 16 + r0 + half * 8;
                float v0 = (c[mi][ni][half * 2 + 0] + b0) * scale;
                float v1 = (c[mi][ni][half * 2 + 1] + b1) * scale;
                int bb = row >> 11, n = row & (NSEQ - 1);
                size_t idx = (((size_t)(bb * NH + hh)) * NSEQ + n) * HD + d;
                unsigned ph, pl;
                if (z == 0) {
                    split_pack_h(v0, v1, ph, pl);
                    *(unsigned*)&gQh[idx] = ph;
                    *(unsigned*)&gQl[idx] = pl;
                } else if (z == 1) {
                    *(unsigned*)&gK[idx] = pack_h2(v0, v1);
                } else {
                    split_pack_h(v0, v1, ph, pl);
                    *(unsigned*)&gVh16[idx] = ph;
                    *(unsigned*)&gVl16[idx] = pl;
                }
            }
        }
    }
}

// ---------------- output projection GEMM (2-term fp16) ---------------------
__global__ __launch_bounds__(256, 2) void gemm_out(
    const float* __restrict__ bo, float* __restrict__ out)
{
    __shared__ __half sA[2][2][128*SAPAD];
    __shared__ __half sB[2][128*SAPAD];

    const __half* Wp = gW + 3 * WELEM;

    const int tid = threadIdx.x, lane = tid & 31, warp = tid >> 5;
    const int m0 = blockIdx.y * 128, n0 = blockIdx.x * 128;
    const int wm = (warp & 1) * 64, wn = (warp >> 1) * 32;

    const int lrow = tid >> 1, lch = (tid & 1) * 8;
    const __half* gAh = gOh + (size_t)(m0 + lrow) * DM + lch;
    const __half* gAl = gOl + (size_t)(m0 + lrow) * DM + lch;
    const __half* gB  = Wp + (size_t)(n0 + lrow) * DM + lch;
    const int so = lrow * SAPAD + lch;

    float c[4][4][4];
    #pragma unroll
    for (int i = 0; i < 4; i++)
        #pragma unroll
        for (int j = 0; j < 4; j++)
            #pragma unroll
            for (int r = 0; r < 4; r++) c[i][j][r] = 0.0f;

    cp16(&sA[0][0][so], gAh); cp16(&sA[0][1][so], gAl);
    cp16(&sB[0][so], gB);
    CP_COMMIT();

    const int ar = lane & 15, ac = (lane >> 4) * 8;
    const int br = lane & 7,  bc = ((lane >> 3) & 1) * 8;

    for (int kt = 0; kt < 64; kt++) {
        const int st = kt & 1;
        CP_WAIT0();
        __syncthreads();
        if (kt < 63) {
            int ko = (kt + 1) * 16;
            cp16(&sA[st ^ 1][0][so], gAh + ko); cp16(&sA[st ^ 1][1][so], gAl + ko);
            cp16(&sB[st ^ 1][so], gB + ko);
            CP_COMMIT();
        }

        unsigned bf[4][2];
        #pragma unroll
        for (int ni = 0; ni < 4; ni++) {
            int off = (wn + ni * 8 + br) * SAPAD + bc;
            ldm_x2(bf[ni][0], bf[ni][1], &sB[st][off]);
        }
        GEMM_PAIR_BODY(0)
        GEMM_PAIR_BODY(1)
    }

    const int r0 = lane >> 2, cq = (lane & 3) * 2;
    #pragma unroll
    for (int mi = 0; mi < 4; mi++) {
        #pragma unroll
        for (int ni = 0; ni < 4; ni++) {
            int col = n0 + wn + ni * 8 + cq;
            float b0 = bo[col], b1 = bo[col + 1];
            #pragma unroll
            for (int half = 0; half < 2; half++) {
                int row = m0 + wm + mi * 16 + r0 + half * 8;
                float2 v = make_float2(c[mi][ni][half * 2 + 0] + b0,
                                       c[mi][ni][half * 2 + 1] + b1);
                *(float2*)&out[(size_t)row * DM + col] = v;
            }
        }
    }
}

// ---------------- flash attention -------------------------------------------
// S: Q fp16-pair x K fp16-single (2 MMAs). PV: P fp16 x V fp16-pair (2 MMAs).
// XOR-swizzled smem: Q 2x128x64, KV 2 stages x 3 x 64x64. 81,920 B -> 2 CTAs/SM.
#define QTSZ   (128*64)              // elems per Q tile
#define KVTSZ  (64*64)               // elems per K/V tile
#define KVSTG  (3*KVTSZ)             // elems per KV stage [K, Vh, Vl]
#define FLASH_SMEM ((2*QTSZ + 2*KVSTG) * 2)   // bytes = 81920

__global__ __launch_bounds__(256, 2) void flash()
{
    extern __shared__ __half sm[];
    __half* sQh = sm;                 // [128x64] swizzled
    __half* sQl = sm + QTSZ;
    __half* sKV = sm + 2 * QTSZ;      // [stage][K,Vh,Vl][64x64]

    const int tid = threadIdx.x, lane = tid & 31, warp = tid >> 5;
    const int bh = blockIdx.y, q0 = blockIdx.x * 128;
    const size_t base = (size_t)bh * NSEQ * HD;

    // Q tiles: 2 x 1024 chunks; 8 per thread
    #pragma unroll
    for (int u = 0; u < 8; u++) {
        int id = tid + u * 256;
        int t = id >> 10, rem = id & 1023;
        int r = rem >> 3, c8 = rem & 7;
        const __half* src = (t == 0) ? gQh : gQl;
        __half* dst = (t == 0) ? sQh : sQl;
        cp16(&dst[swz64(r, c8)], src + base + (size_t)(q0 + r) * HD + c8 * 8);
    }
    // KV stage 0: 3 x 512 chunks; 6 per thread
    #pragma unroll
    for (int u = 0; u < 6; u++) {
        int id = tid + u * 256;
        int t = id >> 9, rem = id & 511;
        int r = rem >> 3, c8 = rem & 7;
        size_t g = base + (size_t)r * HD + c8 * 8;
        const void* src = (t == 0) ? (const void*)(gK + g)
                        : (t == 1) ? (const void*)(gVh16 + g)
                                   : (const void*)(gVl16 + g);
        cp16(&sKV[t * KVTSZ + swz64(r, c8)], src);
    }
    CP_COMMIT();

    float o[8][4];
    #pragma unroll
    for (int i = 0; i < 8; i++)
        #pragma unroll
        for (int j = 0; j < 4; j++) o[i][j] = 0.0f;
    float mr0 = -1e30f, mr1 = -1e30f, lr0 = 0.0f, lr1 = 0.0f;

    const int ar = lane & 15;
    const int achk = lane >> 4;          // A-operand chunk half
    const int br = lane & 7;
    const int bchk = (lane >> 3) & 1;    // B-operand chunk half

    for (int kt = 0; kt < NSEQ / 64; kt++) {
        const int st = kt & 1;
        CP_WAIT0();
        __syncthreads();
        if (kt < NSEQ / 64 - 1) {
            __half* d = sKV + (st ^ 1) * KVSTG;
            size_t kb = base + (size_t)(kt + 1) * 64 * HD;
            #pragma unroll
            for (int u = 0; u < 6; u++) {
                int id = tid + u * 256;
                int t = id >> 9, rem = id & 511;
                int r = rem >> 3, c8 = rem & 7;
                size_t g = kb + (size_t)r * HD + c8 * 8;
                const void* src = (t == 0) ? (const void*)(gK + g)
                                : (t == 1) ? (const void*)(gVh16 + g)
                                           : (const void*)(gVl16 + g);
                cp16(&d[t * KVTSZ + swz64(r, c8)], src);
            }
            CP_COMMIT();
        }

        const __half* Ks = sKV + st * KVSTG;
        const __half* Vh = Ks + KVTSZ;
        const __half* Vl = Ks + 2 * KVTSZ;

        float s[8][4];
        #pragma unroll
        for (int i = 0; i < 8; i++)
            #pragma unroll
            for (int j = 0; j < 4; j++) s[i][j] = 0.0f;

        // S = Q.K^T — 2 terms, term-major over ni-quads
        #pragma unroll
        for (int kk = 0; kk < 4; kk++) {
            unsigned ah[4], al[4];
            int arow = warp * 16 + ar;
            int aoff = swz64(arow, kk * 2 + achk);
            ldm_x4(ah[0], ah[1], ah[2], ah[3], &sQh[aoff]);
            ldm_x4(al[0], al[1], al[2], al[3], &sQl[aoff]);
            #pragma unroll
            for (int nh = 0; nh < 2; nh++) {
                unsigned kb4[4][2];
                #pragma unroll
                for (int nq = 0; nq < 4; nq++) {
                    int krow = (nh * 4 + nq) * 8 + br;
                    int koff = swz64(krow, kk * 2 + bchk);
                    ldm_x2(kb4[nq][0], kb4[nq][1], &Ks[koff]);
                }
                #pragma unroll
                for (int nq = 0; nq < 4; nq++)
                    mma16816h(s[nh * 4 + nq], ah[0], ah[1], ah[2], ah[3],
                              kb4[nq][0], kb4[nq][1]);
                #pragma unroll
                for (int nq = 0; nq < 4; nq++)
                    mma16816h(s[nh * 4 + nq], al[0], al[1], al[2], al[3],
                              kb4[nq][0], kb4[nq][1]);
            }
        }

        float mx0 = -1e30f, mx1 = -1e30f;
        #pragma unroll
        for (int ni = 0; ni < 8; ni++) {
            mx0 = fmaxf(mx0, fmaxf(s[ni][0], s[ni][1]));
            mx1 = fmaxf(mx1, fmaxf(s[ni][2], s[ni][3]));
        }
        mx0 = fmaxf(mx0, __shfl_xor_sync(0xffffffffu, mx0, 1));
        mx0 = fmaxf(mx0, __shfl_xor_sync(0xffffffffu, mx0, 2));
        mx1 = fmaxf(mx1, __shfl_xor_sync(0xffffffffu, mx1, 1));
        mx1 = fmaxf(mx1, __shfl_xor_sync(0xffffffffu, mx1, 2));

        float nm0 = fmaxf(mr0, mx0), nm1 = fmaxf(mr1, mx1);
        float cr0 = __expf(mr0 - nm0), cr1 = __expf(mr1 - nm1);
        mr0 = nm0; mr1 = nm1;

        float sum0 = 0.0f, sum1 = 0.0f;
        #pragma unroll
        for (int ni = 0; ni < 8; ni++) {
            s[ni][0] = __expf(s[ni][0] - nm0);
            s[ni][1] = __expf(s[ni][1] - nm0);
            s[ni][2] = __expf(s[ni][2] - nm1);
            s[ni][3] = __expf(s[ni][3] - nm1);
            sum0 += s[ni][0] + s[ni][1];
            sum1 += s[ni][2] + s[ni][3];
        }
        sum0 += __shfl_xor_sync(0xffffffffu, sum0, 1);
        sum0 += __shfl_xor_sync(0xffffffffu, sum0, 2);
        sum1 += __shfl_xor_sync(0xffffffffu, sum1, 1);
        sum1 += __shfl_xor_sync(0xffffffffu, sum1, 2);
        lr0 = lr0 * cr0 + sum0;
        lr1 = lr1 * cr1 + sum1;
        #pragma unroll
        for (int dj = 0; dj < 8; dj++) {
            o[dj][0] *= cr0; o[dj][1] *= cr0;
            o[dj][2] *= cr1; o[dj][3] *= cr1;
        }

        // O += P(fp16) . V(fp16 hi+lo) — term-major over dj-quads
        #pragma unroll
        for (int kk = 0; kk < 4; kk++) {
            unsigned p0 = pack_h2(s[2*kk][0],   s[2*kk][1]);
            unsigned p1 = pack_h2(s[2*kk][2],   s[2*kk][3]);
            unsigned p2 = pack_h2(s[2*kk+1][0], s[2*kk+1][1]);
            unsigned p3 = pack_h2(s[2*kk+1][2], s[2*kk+1][3]);
            int vrow = kk * 16 + ar;
            #pragma unroll
            for (int dh = 0; dh < 2; dh++) {
                unsigned vb4[4][2], vc4[4][2];
                #pragma unroll
                for (int dq = 0; dq < 4; dq++) {
                    int voff = swz64(vrow, dh * 4 + dq);
                    ldm_x2t(vb4[dq][0], vb4[dq][1], &Vh[voff]);
                    ldm_x2t(vc4[dq][0], vc4[dq][1], &Vl[voff]);
                }
                #pragma unroll
                for (int dq = 0; dq < 4; dq++)
                    mma16816h(o[dh * 4 + dq], p0, p1, p2, p3,
                              vb4[dq][0], vb4[dq][1]);
                #pragma unroll
                for (int dq = 0; dq < 4; dq++)
                    mma16816h(o[dh * 4 + dq], p0, p1, p2, p3,
                              vc4[dq][0], vc4[dq][1]);
            }
        }
    }

    const int b = bh >> 4, h = bh & 15;
    const int row0 = q0 + warp * 16 + (lane >> 2);
    const float inv0 = 1.0f / lr0, inv1 = 1.0f / lr1;
    const size_t rb = ((size_t)(b * NSEQ) + row0) * DM + h * HD;
    #pragma unroll
    for (int dj = 0; dj < 8; dj++) {
        int d = dj * 8 + (lane & 3) * 2;
        unsigned ph, pl;
        split_pack_h(o[dj][0] * inv0, o[dj][1] * inv0, ph, pl);
        *(unsigned*)&gOh[rb + d] = ph;
        *(unsigned*)&gOl[rb + d] = pl;
        split_pack_h(o[dj][2] * inv1, o[dj][3] * inv1, ph, pl);
        *(unsigned*)&gOh[rb + (size_t)8 * DM + d] = ph;
        *(unsigned*)&gOl[rb + (size_t)8 * DM + d] = pl;
    }
}

// ---------------------------------------------------------------------------
extern "C" void kernel_launch(void* const* d_in, const int* in_sizes, int n_in,
                              void* d_out, int out_size)
{
    (void)in_sizes; (void)n_in; (void)out_size;
    const float* queries = (const float*)d_in[0];
    const float* keys    = (const float*)d_in[1];
    const float* values  = (const float*)d_in[2];
    const float* Wq = (const float*)d_in[3];
    const float* bq = (const float*)d_in[4];
    const float* Wk = (const float*)d_in[5];
    const float* bk = (const float*)d_in[6];
    const float* Wv = (const float*)d_in[7];
    const float* bv = (const float*)d_in[8];
    const float* Wo = (const float*)d_in[9];
    const float* bo = (const float*)d_in[10];
    float* out = (float*)d_out;

    cudaFuncSetAttribute(flash, cudaFuncAttributeMaxDynamicSharedMemorySize,
                         FLASH_SMEM);

    // fp32 -> fp16 split (single launch)
    split_all<<<2048, 256>>>(queries, keys, values, Wq, Wk, Wv, Wo);

    // QKV projections
    gemm_qkv<<<dim3(DM / 128, MROWS / 128, 3), 256>>>(bq, bk, bv);

    // attention
    flash<<<dim3(NSEQ / 128, NB * NH), 256, FLASH_SMEM>>>();

    // output projection
    gemm_out<<<dim3(DM / 128, MROWS / 128), 256>>>(bo, out);
}

// round 8
// speedup vs baseline: 1.4910x; 1.1020x over previous
#include <cuda_runtime.h>
#include <cuda_bf16.h>
#include <cuda_fp16.h>
#include <math.h>
#include <stdint.h>

#define DM   1024
#define NSEQ 2048
#define NB   2
#define NH   16
#define HD   64
#define MROWS (NB*NSEQ)          // 4096
#define NELEM ((size_t)MROWS*DM) // 4,194,304
#define WELEM ((size_t)DM*DM)    // 1,048,576

// ---------------- scratch (__device__ globals; no allocations) -------------
__device__ __half gXh[3*NELEM], gXl[3*NELEM]; // split inputs q,k,v (fp16 pair)
__device__ __half gW[4*WELEM];                // weights single fp16
__device__ __half gQh[NELEM], gQl[NELEM];     // (b,h,n,d), Q pre-scaled, pair
__device__ __half gK[NELEM];                  // K single fp16
__device__ __half gV[NELEM];                  // V single fp16
__device__ __half gOh[NELEM], gOl[NELEM];     // attn out (b*n, h*d), pair

// ---------------- PTX helpers ---------------------------------------------
__device__ __forceinline__ void mma16816h(float* c,
    unsigned a0, unsigned a1, unsigned a2, unsigned a3,
    unsigned b0, unsigned b1)
{
    asm volatile(
        "mma.sync.aligned.m16n8k16.row.col.f32.f16.f16.f32 "
        "{%0,%1,%2,%3},{%4,%5,%6,%7},{%8,%9},{%0,%1,%2,%3};"
        : "+f"(c[0]), "+f"(c[1]), "+f"(c[2]), "+f"(c[3])
        : "r"(a0), "r"(a1), "r"(a2), "r"(a3), "r"(b0), "r"(b1));
}

__device__ __forceinline__ void ldm_x4(unsigned& r0, unsigned& r1,
                                       unsigned& r2, unsigned& r3,
                                       const void* p)
{
    unsigned a = (unsigned)__cvta_generic_to_shared(p);
    asm volatile("ldmatrix.sync.aligned.m8n8.x4.shared.b16 {%0,%1,%2,%3},[%4];"
                 : "=r"(r0), "=r"(r1), "=r"(r2), "=r"(r3) : "r"(a));
}

__device__ __forceinline__ void ldm_x2(unsigned& r0, unsigned& r1, const void* p)
{
    unsigned a = (unsigned)__cvta_generic_to_shared(p);
    asm volatile("ldmatrix.sync.aligned.m8n8.x2.shared.b16 {%0,%1},[%2];"
                 : "=r"(r0), "=r"(r1) : "r"(a));
}

__device__ __forceinline__ void ldm_x2t(unsigned& r0, unsigned& r1, const void* p)
{
    unsigned a = (unsigned)__cvta_generic_to_shared(p);
    asm volatile("ldmatrix.sync.aligned.m8n8.x2.trans.shared.b16 {%0,%1},[%2];"
                 : "=r"(r0), "=r"(r1) : "r"(a));
}

__device__ __forceinline__ void cp16(void* dst, const void* src)
{
    unsigned d = (unsigned)__cvta_generic_to_shared(dst);
    asm volatile("cp.async.cg.shared.global [%0], [%1], 16;" :: "r"(d), "l"(src));
}
#define CP_COMMIT() asm volatile("cp.async.commit_group;")
#define CP_WAIT0()  asm volatile("cp.async.wait_group 0;")

// split fp32 pair -> packed fp16x2 hi + fp16x2 lo
__device__ __forceinline__ void split_pack_h(float x, float y,
                                             unsigned& h, unsigned& l)
{
    __half hx = __float2half_rn(x);
    __half hy = __float2half_rn(y);
    float rx = x - __half2float(hx);
    float ry = y - __half2float(hy);
    __half2 hp = __halves2half2(hx, hy);
    __half2 lp = __halves2half2(__float2half_rn(rx), __float2half_rn(ry));
    h = *(unsigned*)&hp;
    l = *(unsigned*)&lp;
}

__device__ __forceinline__ unsigned pack_h2(float x, float y)
{
    __half2 p = __floats2half2_rn(x, y);
    return *(unsigned*)&p;
}

// 16B-chunk XOR swizzle for 64-col fp16 tiles (row*64 elems + chunk^row&7)
__device__ __forceinline__ int swz64(int r, int c8)
{
    return r * 64 + ((c8 ^ (r & 7)) * 8);
}

// ---------------- merged fp32 -> fp16 conversion (single launch) -----------
#define NF4_IN (NELEM >> 2)   // 2^20 float4 per input tensor
#define NF4_W  (WELEM >> 2)   // 2^18 float4 per weight tensor
#define NF4_TOT (3*NF4_IN + 4*NF4_W)

__global__ void split_all(const float* __restrict__ q, const float* __restrict__ k,
                          const float* __restrict__ v, const float* __restrict__ wq,
                          const float* __restrict__ wk, const float* __restrict__ wv,
                          const float* __restrict__ wo)
{
    for (size_t i = blockIdx.x * blockDim.x + threadIdx.x; i < NF4_TOT;
         i += (size_t)gridDim.x * blockDim.x) {
        if (i < 3*NF4_IN) {
            int slot = (int)(i >> 20);
            size_t off = i & (NF4_IN - 1);
            const float* src = (slot == 0) ? q : (slot == 1) ? k : v;
            __half* h = gXh + (size_t)slot * NELEM;
            __half* l = gXl + (size_t)slot * NELEM;
            float4 val = ((const float4*)src)[off];
            unsigned h0, l0, h1, l1;
            split_pack_h(val.x, val.y, h0, l0);
            split_pack_h(val.z, val.w, h1, l1);
            ((uint2*)h)[off] = make_uint2(h0, h1);
            ((uint2*)l)[off] = make_uint2(l0, l1);
        } else {
            size_t j = i - 3*NF4_IN;
            int slot = (int)(j >> 18);
            size_t off = j & (NF4_W - 1);
            const float* src = (slot == 0) ? wq : (slot == 1) ? wk
                             : (slot == 2) ? wv : wo;
            __half* h = gW + (size_t)slot * WELEM;
            float4 val = ((const float4*)src)[off];
            ((uint2*)h)[off] = make_uint2(pack_h2(val.x, val.y),
                                          pack_h2(val.z, val.w));
        }
    }
}

// ---------------- GEMM mainloop body (2-term, term-major order) ------------
#define GEMM_PAIR_BODY(mp)                                                    \
    {                                                                         \
        unsigned ah[2][4], al[2][4];                                          \
        _Pragma("unroll")                                                     \
        for (int q = 0; q < 2; q++) {                                         \
            int off = (wm + ((mp)*2 + q) * 16 + ar) * SAPAD + ac;             \
            ldm_x4(ah[q][0], ah[q][1], ah[q][2], ah[q][3], &sA[st][0][off]);  \
            ldm_x4(al[q][0], al[q][1], al[q][2], al[q][3], &sA[st][1][off]);  \
        }                                                                     \
        _Pragma("unroll")                                                     \
        for (int q = 0; q < 2; q++)                                           \
            _Pragma("unroll")                                                 \
            for (int ni = 0; ni < 4; ni++)                                    \
                mma16816h(c[(mp)*2 + q][ni], ah[q][0], ah[q][1], ah[q][2],    \
                          ah[q][3], bf[ni][0], bf[ni][1]);                    \
        _Pragma("unroll")                                                     \
        for (int q = 0; q < 2; q++)                                           \
            _Pragma("unroll")                                                 \
            for (int ni = 0; ni < 4; ni++)                                    \
                mma16816h(c[(mp)*2 + q][ni], al[q][0], al[q][1], al[q][2],    \
                          al[q][3], bf[ni][0], bf[ni][1]);                    \
    }

// ---------------- QKV projection GEMM (2-term fp16 tensor cores) -----------
#define SAPAD 24

__global__ __launch_bounds__(256, 2) void gemm_qkv(
    const float* __restrict__ bq, const float* __restrict__ bk,
    const float* __restrict__ bv)
{
    __shared__ __half sA[2][2][128*SAPAD];
    __shared__ __half sB[2][128*SAPAD];

    const int z = blockIdx.z;
    const __half* Xh = gXh + (size_t)z * NELEM;
    const __half* Xl = gXl + (size_t)z * NELEM;
    const __half* Wp = gW + (size_t)z * WELEM;
    const float* bias = (z == 0) ? bq : (z == 1) ? bk : bv;
    const float scale = (z == 0) ? 0.125f : 1.0f;

    const int tid = threadIdx.x, lane = tid & 31, warp = tid >> 5;
    const int m0 = blockIdx.y * 128, n0 = blockIdx.x * 128;
    const int wm = (warp & 1) * 64, wn = (warp >> 1) * 32;

    const int lrow = tid >> 1, lch = (tid & 1) * 8;
    const __half* gAh = Xh + (size_t)(m0 + lrow) * DM + lch;
    const __half* gAl = Xl + (size_t)(m0 + lrow) * DM + lch;
    const __half* gB  = Wp + (size_t)(n0 + lrow) * DM + lch;
    const int so = lrow * SAPAD + lch;

    float c[4][4][4];
    #pragma unroll
    for (int i = 0; i < 4; i++)
        #pragma unroll
        for (int j = 0; j < 4; j++)
            #pragma unroll
            for (int r = 0; r < 4; r++) c[i][j][r] = 0.0f;

    cp16(&sA[0][0][so], gAh); cp16(&sA[0][1][so], gAl);
    cp16(&sB[0][so], gB);
    CP_COMMIT();

    const int ar = lane & 15, ac = (lane >> 4) * 8;
    const int br = lane & 7,  bc = ((lane >> 3) & 1) * 8;

    for (int kt = 0; kt < 64; kt++) {
        const int st = kt & 1;
        CP_WAIT0();
        __syncthreads();
        if (kt < 63) {
            int ko = (kt + 1) * 16;
            cp16(&sA[st ^ 1][0][so], gAh + ko); cp16(&sA[st ^ 1][1][so], gAl + ko);
            cp16(&sB[st ^ 1][so], gB + ko);
            CP_COMMIT();
        }

        unsigned bf[4][2];
        #pragma unroll
        for (int ni = 0; ni < 4; ni++) {
            int off = (wn + ni * 8 + br) * SAPAD + bc;
            ldm_x2(bf[ni][0], bf[ni][1], &sB[st][off]);
        }
        GEMM_PAIR_BODY(0)
        GEMM_PAIR_BODY(1)
    }

    // epilogue: + bias, * scale(Q), convert, scatter to (b,h,n,d)
    const int r0 = lane >> 2, cq = (lane & 3) * 2;
    #pragma unroll
    for (int mi = 0; mi < 4; mi++) {
        #pragma unroll
        for (int ni = 0; ni < 4; ni++) {
            int col = n0 + wn + ni * 8 + cq;
            float b0 = bias[col], b1 = bias[col + 1];
            int hh = col >> 6, d = col & 63;
            #pragma unroll
            for (int half = 0; half < 2; half++) {
                int row = m0 + wm + mi * 16 + r0 + half * 8;
                float v0 = (c[mi][ni][half * 2 + 0] + b0) * scale;
                float v1 = (c[mi][ni][half * 2 + 1] + b1) * scale;
                int bb = row >> 11, n = row & (NSEQ - 1);
                size_t idx = (((size_t)(bb * NH + hh)) * NSEQ + n) * HD + d;
                if (z == 0) {
                    unsigned ph, pl;
                    split_pack_h(v0, v1, ph, pl);
                    *(unsigned*)&gQh[idx] = ph;
                    *(unsigned*)&gQl[idx] = pl;
                } else if (z == 1) {
                    *(unsigned*)&gK[idx] = pack_h2(v0, v1);
                } else {
                    *(unsigned*)&gV[idx] = pack_h2(v0, v1);
                }
            }
        }
    }
}

// ---------------- output projection GEMM (2-term fp16) ---------------------
__global__ __launch_bounds__(256, 2) void gemm_out(
    const float* __restrict__ bo, float* __restrict__ out)
{
    __shared__ __half sA[2][2][128*SAPAD];
    __shared__ __half sB[2][128*SAPAD];

    const __half* Wp = gW + 3 * WELEM;

    const int tid = threadIdx.x, lane = tid & 31, warp = tid >> 5;
    const int m0 = blockIdx.y * 128, n0 = blockIdx.x * 128;
    const int wm = (warp & 1) * 64, wn = (warp >> 1) * 32;

    const int lrow = tid >> 1, lch = (tid & 1) * 8;
    const __half* gAh = gOh + (size_t)(m0 + lrow) * DM + lch;
    const __half* gAl = gOl + (size_t)(m0 + lrow) * DM + lch;
    const __half* gB  = Wp + (size_t)(n0 + lrow) * DM + lch;
    const int so = lrow * SAPAD + lch;

    float c[4][4][4];
    #pragma unroll
    for (int i = 0; i < 4; i++)
        #pragma unroll
        for (int j = 0; j < 4; j++)
            #pragma unroll
            for (int r = 0; r < 4; r++) c[i][j][r] = 0.0f;

    cp16(&sA[0][0][so], gAh); cp16(&sA[0][1][so], gAl);
    cp16(&sB[0][so], gB);
    CP_COMMIT();

    const int ar = lane & 15, ac = (lane >> 4) * 8;
    const int br = lane & 7,  bc = ((lane >> 3) & 1) * 8;

    for (int kt = 0; kt < 64; kt++) {
        const int st = kt & 1;
        CP_WAIT0();
        __syncthreads();
        if (kt < 63) {
            int ko = (kt + 1) * 16;
            cp16(&sA[st ^ 1][0][so], gAh + ko); cp16(&sA[st ^ 1][1][so], gAl + ko);
            cp16(&sB[st ^ 1][so], gB + ko);
            CP_COMMIT();
        }

        unsigned bf[4][2];
        #pragma unroll
        for (int ni = 0; ni < 4; ni++) {
            int off = (wn + ni * 8 + br) * SAPAD + bc;
            ldm_x2(bf[ni][0], bf[ni][1], &sB[st][off]);
        }
        GEMM_PAIR_BODY(0)
        GEMM_PAIR_BODY(1)
    }

    const int r0 = lane >> 2, cq = (lane & 3) * 2;
    #pragma unroll
    for (int mi = 0; mi < 4; mi++) {
        #pragma unroll
        for (int ni = 0; ni < 4; ni++) {
            int col = n0 + wn + ni * 8 + cq;
            float b0 = bo[col], b1 = bo[col + 1];
            #pragma unroll
            for (int half = 0; half < 2; half++) {
                int row = m0 + wm + mi * 16 + r0 + half * 8;
                float2 v = make_float2(c[mi][ni][half * 2 + 0] + b0,
                                       c[mi][ni][half * 2 + 1] + b1);
                *(float2*)&out[(size_t)row * DM + col] = v;
            }
        }
    }
}

// ---------------- flash attention -------------------------------------------
// S: Q fp16-pair x K fp16-single (2 MMAs). PV: P fp16 x V fp16-single (1 MMA).
// XOR-swizzled smem: Q 2x128x64, KV 2 stages x 2 x 64x64. 65,536 B -> 2 CTAs/SM.
#define QTSZ   (128*64)              // elems per Q tile
#define KVTSZ  (64*64)               // elems per K/V tile
#define KVSTG  (2*KVTSZ)             // elems per KV stage [K, V]
#define FLASH_SMEM ((2*QTSZ + 2*KVSTG) * 2)   // bytes = 65536

__global__ __launch_bounds__(256, 2) void flash()
{
    extern __shared__ __half sm[];
    __half* sQh = sm;                 // [128x64] swizzled
    __half* sQl = sm + QTSZ;
    __half* sKV = sm + 2 * QTSZ;      // [stage][K,V][64x64]

    const int tid = threadIdx.x, lane = tid & 31, warp = tid >> 5;
    const int bh = blockIdx.y, q0 = blockIdx.x * 128;
    const size_t base = (size_t)bh * NSEQ * HD;

    // Q tiles: 2 x 1024 chunks; 8 per thread
    #pragma unroll
    for (int u = 0; u < 8; u++) {
        int id = tid + u * 256;
        int t = id >> 10, rem = id & 1023;
        int r = rem >> 3, c8 = rem & 7;
        const __half* src = (t == 0) ? gQh : gQl;
        __half* dst = (t == 0) ? sQh : sQl;
        cp16(&dst[swz64(r, c8)], src + base + (size_t)(q0 + r) * HD + c8 * 8);
    }
    // KV stage 0: 2 x 512 chunks; 4 per thread
    #pragma unroll
    for (int u = 0; u < 4; u++) {
        int id = tid + u * 256;
        int t = id >> 9, rem = id & 511;
        int r = rem >> 3, c8 = rem & 7;
        size_t g = base + (size_t)r * HD + c8 * 8;
        const void* src = (t == 0) ? (const void*)(gK + g)
                                   : (const void*)(gV + g);
        cp16(&sKV[t * KVTSZ + swz64(r, c8)], src);
    }
    CP_COMMIT();

    float o[8][4];
    #pragma unroll
    for (int i = 0; i < 8; i++)
        #pragma unroll
        for (int j = 0; j < 4; j++) o[i][j] = 0.0f;
    float mr0 = -1e30f, mr1 = -1e30f, lr0 = 0.0f, lr1 = 0.0f;

    const int ar = lane & 15;
    const int achk = lane >> 4;          // A-operand chunk half
    const int br = lane & 7;
    const int bchk = (lane >> 3) & 1;    // B-operand chunk half

    for (int kt = 0; kt < NSEQ / 64; kt++) {
        const int st = kt & 1;
        CP_WAIT0();
        __syncthreads();
        if (kt < NSEQ / 64 - 1) {
            __half* d = sKV + (st ^ 1) * KVSTG;
            size_t kb = base + (size_t)(kt + 1) * 64 * HD;
            #pragma unroll
            for (int u = 0; u < 4; u++) {
                int id = tid + u * 256;
                int t = id >> 9, rem = id & 511;
                int r = rem >> 3, c8 = rem & 7;
                size_t g = kb + (size_t)r * HD + c8 * 8;
                const void* src = (t == 0) ? (const void*)(gK + g)
                                           : (const void*)(gV + g);
                cp16(&d[t * KVTSZ + swz64(r, c8)], src);
            }
            CP_COMMIT();
        }

        const __half* Ks = sKV + st * KVSTG;
        const __half* Vs = Ks + KVTSZ;

        float s[8][4];
        #pragma unroll
        for (int i = 0; i < 8; i++)
            #pragma unroll
            for (int j = 0; j < 4; j++) s[i][j] = 0.0f;

        // S = Q.K^T — 2 terms, term-major over ni-quads
        #pragma unroll
        for (int kk = 0; kk < 4; kk++) {
            unsigned ah[4], al[4];
            int arow = warp * 16 + ar;
            int aoff = swz64(arow, kk * 2 + achk);
            ldm_x4(ah[0], ah[1], ah[2], ah[3], &sQh[aoff]);
            ldm_x4(al[0], al[1], al[2], al[3], &sQl[aoff]);
            #pragma unroll
            for (int nh = 0; nh < 2; nh++) {
                unsigned kb4[4][2];
                #pragma unroll
                for (int nq = 0; nq < 4; nq++) {
                    int krow = (nh * 4 + nq) * 8 + br;
                    int koff = swz64(krow, kk * 2 + bchk);
                    ldm_x2(kb4[nq][0], kb4[nq][1], &Ks[koff]);
                }
                #pragma unroll
                for (int nq = 0; nq < 4; nq++)
                    mma16816h(s[nh * 4 + nq], ah[0], ah[1], ah[2], ah[3],
                              kb4[nq][0], kb4[nq][1]);
                #pragma unroll
                for (int nq = 0; nq < 4; nq++)
                    mma16816h(s[nh * 4 + nq], al[0], al[1], al[2], al[3],
                              kb4[nq][0], kb4[nq][1]);
            }
        }

        float mx0 = -1e30f, mx1 = -1e30f;
        #pragma unroll
        for (int ni = 0; ni < 8; ni++) {
            mx0 = fmaxf(mx0, fmaxf(s[ni][0], s[ni][1]));
            mx1 = fmaxf(mx1, fmaxf(s[ni][2], s[ni][3]));
        }
        mx0 = fmaxf(mx0, __shfl_xor_sync(0xffffffffu, mx0, 1));
        mx0 = fmaxf(mx0, __shfl_xor_sync(0xffffffffu, mx0, 2));
        mx1 = fmaxf(mx1, __shfl_xor_sync(0xffffffffu, mx1, 1));
        mx1 = fmaxf(mx1, __shfl_xor_sync(0xffffffffu, mx1, 2));

        float nm0 = fmaxf(mr0, mx0), nm1 = fmaxf(mr1, mx1);
        float cr0 = __expf(mr0 - nm0), cr1 = __expf(mr1 - nm1);
        mr0 = nm0; mr1 = nm1;

        float sum0 = 0.0f, sum1 = 0.0f;
        #pragma unroll
        for (int ni = 0; ni < 8; ni++) {
            s[ni][0] = __expf(s[ni][0] - nm0);
            s[ni][1] = __expf(s[ni][1] - nm0);
            s[ni][2] = __expf(s[ni][2] - nm1);
            s[ni][3] = __expf(s[ni][3] - nm1);
            sum0 += s[ni][0] + s[ni][1];
            sum1 += s[ni][2] + s[ni][3];
        }
        sum0 += __shfl_xor_sync(0xffffffffu, sum0, 1);
        sum0 += __shfl_xor_sync(0xffffffffu, sum0, 2);
        sum1 += __shfl_xor_sync(0xffffffffu, sum1, 1);
        sum1 += __shfl_xor_sync(0xffffffffu, sum1, 2);
        lr0 = lr0 * cr0 + sum0;
        lr1 = lr1 * cr1 + sum1;
        #pragma unroll
        for (int dj = 0; dj < 8; dj++) {
            o[dj][0] *= cr0; o[dj][1] *= cr0;
            o[dj][2] *= cr1; o[dj][3] *= cr1;
        }

        // O += P(fp16) . V(fp16 single) — term-major over dj-quads
        #pragma unroll
        for (int kk = 0; kk < 4; kk++) {
            unsigned p0 = pack_h2(s[2*kk][0],   s[2*kk][1]);
            unsigned p1 = pack_h2(s[2*kk][2],   s[2*kk][3]);
            unsigned p2 = pack_h2(s[2*kk+1][0], s[2*kk+1][1]);
            unsigned p3 = pack_h2(s[2*kk+1][2], s[2*kk+1][3]);
            int vrow = kk * 16 + ar;
            #pragma unroll
            for (int dh = 0; dh < 2; dh++) {
                unsigned vb4[4][2];
                #pragma unroll
                for (int dq = 0; dq < 4; dq++) {
                    int voff = swz64(vrow, dh * 4 + dq);
                    ldm_x2t(vb4[dq][0], vb4[dq][1], &Vs[voff]);
                }
                #pragma unroll
                for (int dq = 0; dq < 4; dq++)
                    mma16816h(o[dh * 4 + dq], p0, p1, p2, p3,
                              vb4[dq][0], vb4[dq][1]);
            }
        }
    }

    const int b = bh >> 4, h = bh & 15;
    const int row0 = q0 + warp * 16 + (lane >> 2);
    const float inv0 = 1.0f / lr0, inv1 = 1.0f / lr1;
    const size_t rb = ((size_t)(b * NSEQ) + row0) * DM + h * HD;
    #pragma unroll
    for (int dj = 0; dj < 8; dj++) {
        int d = dj * 8 + (lane & 3) * 2;
        unsigned ph, pl;
        split_pack_h(o[dj][0] * inv0, o[dj][1] * inv0, ph, pl);
        *(unsigned*)&gOh[rb + d] = ph;
        *(unsigned*)&gOl[rb + d] = pl;
        split_pack_h(o[dj][2] * inv1, o[dj][3] * inv1, ph, pl);
        *(unsigned*)&gOh[rb + (size_t)8 * DM + d] = ph;
        *(unsigned*)&gOl[rb + (size_t)8 * DM + d] = pl;
    }
}

// ---------------------------------------------------------------------------
extern "C" void kernel_launch(void* const* d_in, const int* in_sizes, int n_in,
                              void* d_out, int out_size)
{
    (void)in_sizes; (void)n_in; (void)out_size;
    const float* queries = (const float*)d_in[0];
    const float* keys    = (const float*)d_in[1];
    const float* values  = (const float*)d_in[2];
    const float* Wq = (const float*)d_in[3];
    const float* bq = (const float*)d_in[4];
    const float* Wk = (const float*)d_in[5];
    const float* bk = (const float*)d_in[6];
    const float* Wv = (const float*)d_in[7];
    const float* bv = (const float*)d_in[8];
    const float* Wo = (const float*)d_in[9];
    const float* bo = (const float*)d_in[10];
    float* out = (float*)d_out;

    cudaFuncSetAttribute(flash, cudaFuncAttributeMaxDynamicSharedMemorySize,
                         FLASH_SMEM);

    // fp32 -> fp16 split (single launch)
    split_all<<<2048, 256>>>(queries, keys, values, Wq, Wk, Wv, Wo);

    // QKV projections
    gemm_qkv<<<dim3(DM / 128, MROWS / 128, 3), 256>>>(bq, bk, bv);

    // attention
    flash<<<dim3(NSEQ / 128, NB * NH), 256, FLASH_SMEM>>>();

    // output projection
    gemm_out<<<dim3(DM / 128, MROWS / 128), 256>>>(bo, out);
}

// round 9
// speedup vs baseline: 1.8921x; 1.2690x over previous
#include <cuda_runtime.h>
#include <cuda_bf16.h>
#include <cuda_fp16.h>
#include <math.h>
#include <stdint.h>

#define DM   1024
#define NSEQ 2048
#define NB   2
#define NH   16
#define HD   64
#define MROWS (NB*NSEQ)          // 4096
#define NELEM ((size_t)MROWS*DM) // 4,194,304
#define WELEM ((size_t)DM*DM)    // 1,048,576

// ---------------- scratch (__device__ globals; no allocations) -------------
__device__ __half gXh[3*NELEM], gXl[NELEM];   // inputs: q pair, k/v single
__device__ __half gW[4*WELEM];                // weights single fp16
__device__ __half gQh[NELEM], gQl[NELEM];     // (b,h,n,d), Q pre-scaled, pair
__device__ __half gK[NELEM];                  // K single fp16
__device__ __half gV[NELEM];                  // V single fp16
__device__ __half gO[NELEM];                  // attn out (b*n, h*d), single

// ---------------- PTX helpers ---------------------------------------------
__device__ __forceinline__ void mma16816h(float* c,
    unsigned a0, unsigned a1, unsigned a2, unsigned a3,
    unsigned b0, unsigned b1)
{
    asm volatile(
        "mma.sync.aligned.m16n8k16.row.col.f32.f16.f16.f32 "
        "{%0,%1,%2,%3},{%4,%5,%6,%7},{%8,%9},{%0,%1,%2,%3};"
        : "+f"(c[0]), "+f"(c[1]), "+f"(c[2]), "+f"(c[3])
        : "r"(a0), "r"(a1), "r"(a2), "r"(a3), "r"(b0), "r"(b1));
}

__device__ __forceinline__ void ldm_x4(unsigned& r0, unsigned& r1,
                                       unsigned& r2, unsigned& r3,
                                       const void* p)
{
    unsigned a = (unsigned)__cvta_generic_to_shared(p);
    asm volatile("ldmatrix.sync.aligned.m8n8.x4.shared.b16 {%0,%1,%2,%3},[%4];"
                 : "=r"(r0), "=r"(r1), "=r"(r2), "=r"(r3) : "r"(a));
}

__device__ __forceinline__ void ldm_x2(unsigned& r0, unsigned& r1, const void* p)
{
    unsigned a = (unsigned)__cvta_generic_to_shared(p);
    asm volatile("ldmatrix.sync.aligned.m8n8.x2.shared.b16 {%0,%1},[%2];"
                 : "=r"(r0), "=r"(r1) : "r"(a));
}

__device__ __forceinline__ void ldm_x2t(unsigned& r0, unsigned& r1, const void* p)
{
    unsigned a = (unsigned)__cvta_generic_to_shared(p);
    asm volatile("ldmatrix.sync.aligned.m8n8.x2.trans.shared.b16 {%0,%1},[%2];"
                 : "=r"(r0), "=r"(r1) : "r"(a));
}

__device__ __forceinline__ void cp16(void* dst, const void* src)
{
    unsigned d = (unsigned)__cvta_generic_to_shared(dst);
    asm volatile("cp.async.cg.shared.global [%0], [%1], 16;" :: "r"(d), "l"(src));
}
#define CP_COMMIT() asm volatile("cp.async.commit_group;")
#define CP_WAIT0()  asm volatile("cp.async.wait_group 0;")

// split fp32 pair -> packed fp16x2 hi + fp16x2 lo
__device__ __forceinline__ void split_pack_h(float x, float y,
                                             unsigned& h, unsigned& l)
{
    __half hx = __float2half_rn(x);
    __half hy = __float2half_rn(y);
    float rx = x - __half2float(hx);
    float ry = y - __half2float(hy);
    __half2 hp = __halves2half2(hx, hy);
    __half2 lp = __halves2half2(__float2half_rn(rx), __float2half_rn(ry));
    h = *(unsigned*)&hp;
    l = *(unsigned*)&lp;
}

__device__ __forceinline__ unsigned pack_h2(float x, float y)
{
    __half2 p = __floats2half2_rn(x, y);
    return *(unsigned*)&p;
}

// 16B-chunk XOR swizzle for 64-col fp16 tiles (row*64 elems + chunk^row&7)
__device__ __forceinline__ int swz64(int r, int c8)
{
    return r * 64 + ((c8 ^ (r & 7)) * 8);
}

// ---------------- merged fp32 -> fp16 conversion (single launch) -----------
#define NF4_IN (NELEM >> 2)   // 2^20 float4 per input tensor
#define NF4_W  (WELEM >> 2)   // 2^18 float4 per weight tensor
#define NF4_TOT (3*NF4_IN + 4*NF4_W)

__global__ void split_all(const float* __restrict__ q, const float* __restrict__ k,
                          const float* __restrict__ v, const float* __restrict__ wq,
                          const float* __restrict__ wk, const float* __restrict__ wv,
                          const float* __restrict__ wo)
{
    for (size_t i = blockIdx.x * blockDim.x + threadIdx.x; i < NF4_TOT;
         i += (size_t)gridDim.x * blockDim.x) {
        if (i < 3*NF4_IN) {
            int slot = (int)(i >> 20);
            size_t off = i & (NF4_IN - 1);
            const float* src = (slot == 0) ? q : (slot == 1) ? k : v;
            __half* h = gXh + (size_t)slot * NELEM;
            float4 val = ((const float4*)src)[off];
            if (slot == 0) {
                unsigned h0, l0, h1, l1;
                split_pack_h(val.x, val.y, h0, l0);
                split_pack_h(val.z, val.w, h1, l1);
                ((uint2*)h)[off]   = make_uint2(h0, h1);
                ((uint2*)gXl)[off] = make_uint2(l0, l1);
            } else {
                ((uint2*)h)[off] = make_uint2(pack_h2(val.x, val.y),
                                              pack_h2(val.z, val.w));
            }
        } else {
            size_t j = i - 3*NF4_IN;
            int slot = (int)(j >> 18);
            size_t off = j & (NF4_W - 1);
            const float* src = (slot == 0) ? wq : (slot == 1) ? wk
                             : (slot == 2) ? wv : wo;
            __half* h = gW + (size_t)slot * WELEM;
            float4 val = ((const float4*)src)[off];
            ((uint2*)h)[off] = make_uint2(pack_h2(val.x, val.y),
                                          pack_h2(val.z, val.w));
        }
    }
}

// ---------------- GEMM mainloop bodies (term-major MMA order) --------------
// 2-term (A hi+lo):
#define GEMM_PAIR_BODY2(mp)                                                   \
    {                                                                         \
        unsigned ah[2][4], al[2][4];                                          \
        _Pragma("unroll")                                                     \
        for (int q = 0; q < 2; q++) {                                         \
            int off = (wm + ((mp)*2 + q) * 16 + ar) * SAPAD + ac;             \
            ldm_x4(ah[q][0], ah[q][1], ah[q][2], ah[q][3], &sA[st][0][off]);  \
            ldm_x4(al[q][0], al[q][1], al[q][2], al[q][3], &sA[st][1][off]);  \
        }                                                                     \
        _Pragma("unroll")                                                     \
        for (int q = 0; q < 2; q++)                                           \
            _Pragma("unroll")                                                 \
            for (int ni = 0; ni < 4; ni++)                                    \
                mma16816h(c[(mp)*2 + q][ni], ah[q][0], ah[q][1], ah[q][2],    \
                          ah[q][3], bf[ni][0], bf[ni][1]);                    \
        _Pragma("unroll")                                                     \
        for (int q = 0; q < 2; q++)                                           \
            _Pragma("unroll")                                                 \
            for (int ni = 0; ni < 4; ni++)                                    \
                mma16816h(c[(mp)*2 + q][ni], al[q][0], al[q][1], al[q][2],    \
                          al[q][3], bf[ni][0], bf[ni][1]);                    \
    }

// 1-term (A hi only):
#define GEMM_PAIR_BODY1(mp)                                                   \
    {                                                                         \
        unsigned ah[2][4];                                                    \
        _Pragma("unroll")                                                     \
        for (int q = 0; q < 2; q++) {                                         \
            int off = (wm + ((mp)*2 + q) * 16 + ar) * SAPAD + ac;             \
            ldm_x4(ah[q][0], ah[q][1], ah[q][2], ah[q][3], &sA[st][0][off]);  \
        }                                                                     \
        _Pragma("unroll")                                                     \
        for (int q = 0; q < 2; q++)                                           \
            _Pragma("unroll")                                                 \
            for (int ni = 0; ni < 4; ni++)                                    \
                mma16816h(c[(mp)*2 + q][ni], ah[q][0], ah[q][1], ah[q][2],    \
                          ah[q][3], bf[ni][0], bf[ni][1]);                    \
    }

// ---------------- QKV projection GEMM --------------------------------------
// z==0 (Q): 2-term A. z==1 (K), z==2 (V): 1-term A.
#define SAPAD 24

__global__ __launch_bounds__(256, 2) void gemm_qkv(
    const float* __restrict__ bq, const float* __restrict__ bk,
    const float* __restrict__ bv)
{
    __shared__ __half sA[2][2][128*SAPAD];
    __shared__ __half sB[2][128*SAPAD];

    const int z = blockIdx.z;
    const __half* Xh = gXh + (size_t)z * NELEM;
    const __half* Wp = gW + (size_t)z * WELEM;
    const float* bias = (z == 0) ? bq : (z == 1) ? bk : bv;
    const float scale = (z == 0) ? 0.125f : 1.0f;

    const int tid = threadIdx.x, lane = tid & 31, warp = tid >> 5;
    const int m0 = blockIdx.y * 128, n0 = blockIdx.x * 128;
    const int wm = (warp & 1) * 64, wn = (warp >> 1) * 32;

    const int lrow = tid >> 1, lch = (tid & 1) * 8;
    const __half* gAh = Xh + (size_t)(m0 + lrow) * DM + lch;
    const __half* gAl = gXl + (size_t)(m0 + lrow) * DM + lch;  // only z==0
    const __half* gB  = Wp + (size_t)(n0 + lrow) * DM + lch;
    const int so = lrow * SAPAD + lch;

    float c[4][4][4];
    #pragma unroll
    for (int i = 0; i < 4; i++)
        #pragma unroll
        for (int j = 0; j < 4; j++)
            #pragma unroll
            for (int r = 0; r < 4; r++) c[i][j][r] = 0.0f;

    cp16(&sA[0][0][so], gAh);
    if (z == 0) cp16(&sA[0][1][so], gAl);
    cp16(&sB[0][so], gB);
    CP_COMMIT();

    const int ar = lane & 15, ac = (lane >> 4) * 8;
    const int br = lane & 7,  bc = ((lane >> 3) & 1) * 8;

    for (int kt = 0; kt < 64; kt++) {
        const int st = kt & 1;
        CP_WAIT0();
        __syncthreads();
        if (kt < 63) {
            int ko = (kt + 1) * 16;
            cp16(&sA[st ^ 1][0][so], gAh + ko);
            if (z == 0) cp16(&sA[st ^ 1][1][so], gAl + ko);
            cp16(&sB[st ^ 1][so], gB + ko);
            CP_COMMIT();
        }

        unsigned bf[4][2];
        #pragma unroll
        for (int ni = 0; ni < 4; ni++) {
            int off = (wn + ni * 8 + br) * SAPAD + bc;
            ldm_x2(bf[ni][0], bf[ni][1], &sB[st][off]);
        }
        if (z == 0) {
            GEMM_PAIR_BODY2(0)
            GEMM_PAIR_BODY2(1)
        } else {
            GEMM_PAIR_BODY1(0)
            GEMM_PAIR_BODY1(1)
        }
    }

    // epilogue: + bias, * scale(Q), convert, scatter to (b,h,n,d)
    const int r0 = lane >> 2, cq = (lane & 3) * 2;
    #pragma unroll
    for (int mi = 0; mi < 4; mi++) {
        #pragma unroll
        for (int ni = 0; ni < 4; ni++) {
            int col = n0 + wn + ni * 8 + cq;
            float b0 = bias[col], b1 = bias[col + 1];
            int hh = col >> 6, d = col & 63;
            #pragma unroll
            for (int half = 0; half < 2; half++) {
                int row = m0 + wm + mi * 16 + r0 + half * 8;
                float v0 = (c[mi][ni][half * 2 + 0] + b0) * scale;
                float v1 = (c[mi][ni][half * 2 + 1] + b1) * scale;
                int bb = row >> 11, n = row & (NSEQ - 1);
                size_t idx = (((size_t)(bb * NH + hh)) * NSEQ + n) * HD + d;
                if (z == 0) {
                    unsigned ph, pl;
                    split_pack_h(v0, v1, ph, pl);
                    *(unsigned*)&gQh[idx] = ph;
                    *(unsigned*)&gQl[idx] = pl;
                } else if (z == 1) {
                    *(unsigned*)&gK[idx] = pack_h2(v0, v1);
                } else {
                    *(unsigned*)&gV[idx] = pack_h2(v0, v1);
                }
            }
        }
    }
}

// ---------------- output projection GEMM (1-term fp16) ---------------------
__global__ __launch_bounds__(256, 2) void gemm_out(
    const float* __restrict__ bo, float* __restrict__ out)
{
    __shared__ __half sA[2][2][128*SAPAD];   // [..][1] unused (layout shared w/ body macro)
    __shared__ __half sB[2][128*SAPAD];

    const __half* Wp = gW + 3 * WELEM;

    const int tid = threadIdx.x, lane = tid & 31, warp = tid >> 5;
    const int m0 = blockIdx.y * 128, n0 = blockIdx.x * 128;
    const int wm = (warp & 1) * 64, wn = (warp >> 1) * 32;

    const int lrow = tid >> 1, lch = (tid & 1) * 8;
    const __half* gAh = gO + (size_t)(m0 + lrow) * DM + lch;
    const __half* gB  = Wp + (size_t)(n0 + lrow) * DM + lch;
    const int so = lrow * SAPAD + lch;

    float c[4][4][4];
    #pragma unroll
    for (int i = 0; i < 4; i++)
        #pragma unroll
        for (int j = 0; j < 4; j++)
            #pragma unroll
            for (int r = 0; r < 4; r++) c[i][j][r] = 0.0f;

    cp16(&sA[0][0][so], gAh);
    cp16(&sB[0][so], gB);
    CP_COMMIT();

    const int ar = lane & 15, ac = (lane >> 4) * 8;
    const int br = lane & 7,  bc = ((lane >> 3) & 1) * 8;

    for (int kt = 0; kt < 64; kt++) {
        const int st = kt & 1;
        CP_WAIT0();
        __syncthreads();
        if (kt < 63) {
            int ko = (kt + 1) * 16;
            cp16(&sA[st ^ 1][0][so], gAh + ko);
            cp16(&sB[st ^ 1][so], gB + ko);
            CP_COMMIT();
        }

        unsigned bf[4][2];
        #pragma unroll
        for (int ni = 0; ni < 4; ni++) {
            int off = (wn + ni * 8 + br) * SAPAD + bc;
            ldm_x2(bf[ni][0], bf[ni][1], &sB[st][off]);
        }
        GEMM_PAIR_BODY1(0)
        GEMM_PAIR_BODY1(1)
    }

    const int r0 = lane >> 2, cq = (lane & 3) * 2;
    #pragma unroll
    for (int mi = 0; mi < 4; mi++) {
        #pragma unroll
        for (int ni = 0; ni < 4; ni++) {
            int col = n0 + wn + ni * 8 + cq;
            float b0 = bo[col], b1 = bo[col + 1];
            #pragma unroll
            for (int half = 0; half < 2; half++) {
                int row = m0 + wm + mi * 16 + r0 + half * 8;
                float2 v = make_float2(c[mi][ni][half * 2 + 0] + b0,
                                       c[mi][ni][half * 2 + 1] + b1);
                *(float2*)&out[(size_t)row * DM + col] = v;
            }
        }
    }
}

// ---------------- flash attention -------------------------------------------
// S: Q fp16-pair x K fp16-single (2 MMAs). PV: P fp16 x V fp16-single (1 MMA).
// XOR-swizzled smem: Q 2x128x64, KV 2 stages x 2 x 64x64. 65,536 B -> 2 CTAs/SM.
#define QTSZ   (128*64)              // elems per Q tile
#define KVTSZ  (64*64)               // elems per K/V tile
#define KVSTG  (2*KVTSZ)             // elems per KV stage [K, V]
#define FLASH_SMEM ((2*QTSZ + 2*KVSTG) * 2)   // bytes = 65536

__global__ __launch_bounds__(256, 2) void flash()
{
    extern __shared__ __half sm[];
    __half* sQh = sm;                 // [128x64] swizzled
    __half* sQl = sm + QTSZ;
    __half* sKV = sm + 2 * QTSZ;      // [stage][K,V][64x64]

    const int tid = threadIdx.x, lane = tid & 31, warp = tid >> 5;
    const int bh = blockIdx.y, q0 = blockIdx.x * 128;
    const size_t base = (size_t)bh * NSEQ * HD;

    // Q tiles: 2 x 1024 chunks; 8 per thread
    #pragma unroll
    for (int u = 0; u < 8; u++) {
        int id = tid + u * 256;
        int t = id >> 10, rem = id & 1023;
        int r = rem >> 3, c8 = rem & 7;
        const __half* src = (t == 0) ? gQh : gQl;
        __half* dst = (t == 0) ? sQh : sQl;
        cp16(&dst[swz64(r, c8)], src + base + (size_t)(q0 + r) * HD + c8 * 8);
    }
    // KV stage 0: 2 x 512 chunks; 4 per thread
    #pragma unroll
    for (int u = 0; u < 4; u++) {
        int id = tid + u * 256;
        int t = id >> 9, rem = id & 511;
        int r = rem >> 3, c8 = rem & 7;
        size_t g = base + (size_t)r * HD + c8 * 8;
        const void* src = (t == 0) ? (const void*)(gK + g)
                                   : (const void*)(gV + g);
        cp16(&sKV[t * KVTSZ + swz64(r, c8)], src);
    }
    CP_COMMIT();

    float o[8][4];
    #pragma unroll
    for (int i = 0; i < 8; i++)
        #pragma unroll
        for (int j = 0; j < 4; j++) o[i][j] = 0.0f;
    float mr0 = -1e30f, mr1 = -1e30f, lr0 = 0.0f, lr1 = 0.0f;

    const int ar = lane & 15;
    const int achk = lane >> 4;          // A-operand chunk half
    const int br = lane & 7;
    const int bchk = (lane >> 3) & 1;    // B-operand chunk half

    for (int kt = 0; kt < NSEQ / 64; kt++) {
        const int st = kt & 1;
        CP_WAIT0();
        __syncthreads();
        if (kt < NSEQ / 64 - 1) {
            __half* d = sKV + (st ^ 1) * KVSTG;
            size_t kb = base + (size_t)(kt + 1) * 64 * HD;
            #pragma unroll
            for (int u = 0; u < 4; u++) {
                int id = tid + u * 256;
                int t = id >> 9, rem = id & 511;
                int r = rem >> 3, c8 = rem & 7;
                size_t g = kb + (size_t)r * HD + c8 * 8;
                const void* src = (t == 0) ? (const void*)(gK + g)
                                           : (const void*)(gV + g);
                cp16(&d[t * KVTSZ + swz64(r, c8)], src);
            }
            CP_COMMIT();
        }

        const __half* Ks = sKV + st * KVSTG;
        const __half* Vs = Ks + KVTSZ;

        float s[8][4];
        #pragma unroll
        for (int i = 0; i < 8; i++)
            #pragma unroll
            for (int j = 0; j < 4; j++) s[i][j] = 0.0f;

        // S = Q.K^T — 2 terms, term-major over ni-quads
        #pragma unroll
        for (int kk = 0; kk < 4; kk++) {
            unsigned ah[4], al[4];
            int arow = warp * 16 + ar;
            int aoff = swz64(arow, kk * 2 + achk);
            ldm_x4(ah[0], ah[1], ah[2], ah[3], &sQh[aoff]);
            ldm_x4(al[0], al[1], al[2], al[3], &sQl[aoff]);
            #pragma unroll
            for (int nh = 0; nh < 2; nh++) {
                unsigned kb4[4][2];
                #pragma unroll
                for (int nq = 0; nq < 4; nq++) {
                    int krow = (nh * 4 + nq) * 8 + br;
                    int koff = swz64(krow, kk * 2 + bchk);
                    ldm_x2(kb4[nq][0], kb4[nq][1], &Ks[koff]);
                }
                #pragma unroll
                for (int nq = 0; nq < 4; nq++)
                    mma16816h(s[nh * 4 + nq], ah[0], ah[1], ah[2], ah[3],
                              kb4[nq][0], kb4[nq][1]);
                #pragma unroll
                for (int nq = 0; nq < 4; nq++)
                    mma16816h(s[nh * 4 + nq], al[0], al[1], al[2], al[3],
                              kb4[nq][0], kb4[nq][1]);
            }
        }

        float mx0 = -1e30f, mx1 = -1e30f;
        #pragma unroll
        for (int ni = 0; ni < 8; ni++) {
            mx0 = fmaxf(mx0, fmaxf(s[ni][0], s[ni][1]));
            mx1 = fmaxf(mx1, fmaxf(s[ni][2], s[ni][3]));
        }
        mx0 = fmaxf(mx0, __shfl_xor_sync(0xffffffffu, mx0, 1));
        mx0 = fmaxf(mx0, __shfl_xor_sync(0xffffffffu, mx0, 2));
        mx1 = fmaxf(mx1, __shfl_xor_sync(0xffffffffu, mx1, 1));
        mx1 = fmaxf(mx1, __shfl_xor_sync(0xffffffffu, mx1, 2));

        float nm0 = fmaxf(mr0, mx0), nm1 = fmaxf(mr1, mx1);
        float cr0 = __expf(mr0 - nm0), cr1 = __expf(mr1 - nm1);
        mr0 = nm0; mr1 = nm1;

        float sum0 = 0.0f, sum1 = 0.0f;
        #pragma unroll
        for (int ni = 0; ni < 8; ni++) {
            s[ni][0] = __expf(s[ni][0] - nm0);
            s[ni][1] = __expf(s[ni][1] - nm0);
            s[ni][2] = __expf(s[ni][2] - nm1);
            s[ni][3] = __expf(s[ni][3] - nm1);
            sum0 += s[ni][0] + s[ni][1];
            sum1 += s[ni][2] + s[ni][3];
        }
        sum0 += __shfl_xor_sync(0xffffffffu, sum0, 1);
        sum0 += __shfl_xor_sync(0xffffffffu, sum0, 2);
        sum1 += __shfl_xor_sync(0xffffffffu, sum1, 1);
        sum1 += __shfl_xor_sync(0xffffffffu, sum1, 2);
        lr0 = lr0 * cr0 + sum0;
        lr1 = lr1 * cr1 + sum1;
        #pragma unroll
        for (int dj = 0; dj < 8; dj++) {
            o[dj][0] *= cr0; o[dj][1] *= cr0;
            o[dj][2] *= cr1; o[dj][3] *= cr1;
        }

        // O += P(fp16) . V(fp16 single) — term-major over dj-quads
        #pragma unroll
        for (int kk = 0; kk < 4; kk++) {
            unsigned p0 = pack_h2(s[2*kk][0],   s[2*kk][1]);
            unsigned p1 = pack_h2(s[2*kk][2],   s[2*kk][3]);
            unsigned p2 = pack_h2(s[2*kk+1][0], s[2*kk+1][1]);
            unsigned p3 = pack_h2(s[2*kk+1][2], s[2*kk+1][3]);
            int vrow = kk * 16 + ar;
            #pragma unroll
            for (int dh = 0; dh < 2; dh++) {
                unsigned vb4[4][2];
                #pragma unroll
                for (int dq = 0; dq < 4; dq++) {
                    int voff = swz64(vrow, dh * 4 + dq);
                    ldm_x2t(vb4[dq][0], vb4[dq][1], &Vs[voff]);
                }
                #pragma unroll
                for (int dq = 0; dq < 4; dq++)
                    mma16816h(o[dh * 4 + dq], p0, p1, p2, p3,
                              vb4[dq][0], vb4[dq][1]);
            }
        }
    }

    const int b = bh >> 4, h = bh & 15;
    const int row0 = q0 + warp * 16 + (lane >> 2);
    const float inv0 = 1.0f / lr0, inv1 = 1.0f / lr1;
    const size_t rb = ((size_t)(b * NSEQ) + row0) * DM + h * HD;
    #pragma unroll
    for (int dj = 0; dj < 8; dj++) {
        int d = dj * 8 + (lane & 3) * 2;
        *(unsigned*)&gO[rb + d] = pack_h2(o[dj][0] * inv0, o[dj][1] * inv0);
        *(unsigned*)&gO[rb + (size_t)8 * DM + d] =
            pack_h2(o[dj][2] * inv1, o[dj][3] * inv1);
    }
}

// ---------------------------------------------------------------------------
extern "C" void kernel_launch(void* const* d_in, const int* in_sizes, int n_in,
                              void* d_out, int out_size)
{
    (void)in_sizes; (void)n_in; (void)out_size;
    const float* queries = (const float*)d_in[0];
    const float* keys    = (const float*)d_in[1];
    const float* values  = (const float*)d_in[2];
    const float* Wq = (const float*)d_in[3];
    const float* bq = (const float*)d_in[4];
    const float* Wk = (const float*)d_in[5];
    const float* bk = (const float*)d_in[6];
    const float* Wv = (const float*)d_in[7];
    const float* bv = (const float*)d_in[8];
    const float* Wo = (const float*)d_in[9];
    const float* bo = (const float*)d_in[10];
    float* out = (float*)d_out;

    cudaFuncSetAttribute(flash, cudaFuncAttributeMaxDynamicSharedMemorySize,
                         FLASH_SMEM);

    // fp32 -> fp16 (single launch; Q split pair, rest single)
    split_all<<<2048, 256>>>(queries, keys, values, Wq, Wk, Wv, Wo);

    // QKV projections
    gemm_qkv<<<dim3(DM / 128, MROWS / 128, 3), 256>>>(bq, bk, bv);

    // attention
    flash<<<dim3(NSEQ / 128, NB * NH), 256, FLASH_SMEM>>>();

    // output projection
    gemm_out<<<dim3(DM / 128, MROWS / 128), 256>>>(bo, out);
}

// round 10
// speedup vs baseline: 2.1473x; 1.1349x over previous
#include <cuda_runtime.h>
#include <cuda_bf16.h>
#include <cuda_fp16.h>
#include <math.h>
#include <stdint.h>

#define DM   1024
#define NSEQ 2048
#define NB   2
#define NH   16
#define HD   64
#define MROWS (NB*NSEQ)          // 4096
#define NELEM ((size_t)MROWS*DM) // 4,194,304
#define WELEM ((size_t)DM*DM)    // 1,048,576

// ---------------- scratch (__device__ globals; no allocations) -------------
__device__ __half gX[3*NELEM];                // inputs q,k,v single fp16
__device__ __half gW[4*WELEM];                // weights single fp16
__device__ __half gQ[NELEM];                  // (b,h,n,d), Q pre-scaled
__device__ __half gK[NELEM];                  // K single fp16
__device__ __half gV[NELEM];                  // V single fp16
__device__ __half gO[NELEM];                  // attn out (b*n, h*d), single

// ---------------- PTX helpers ---------------------------------------------
__device__ __forceinline__ void mma16816h(float* c,
    unsigned a0, unsigned a1, unsigned a2, unsigned a3,
    unsigned b0, unsigned b1)
{
    asm volatile(
        "mma.sync.aligned.m16n8k16.row.col.f32.f16.f16.f32 "
        "{%0,%1,%2,%3},{%4,%5,%6,%7},{%8,%9},{%0,%1,%2,%3};"
        : "+f"(c[0]), "+f"(c[1]), "+f"(c[2]), "+f"(c[3])
        : "r"(a0), "r"(a1), "r"(a2), "r"(a3), "r"(b0), "r"(b1));
}

__device__ __forceinline__ void ldm_x4(unsigned& r0, unsigned& r1,
                                       unsigned& r2, unsigned& r3,
                                       const void* p)
{
    unsigned a = (unsigned)__cvta_generic_to_shared(p);
    asm volatile("ldmatrix.sync.aligned.m8n8.x4.shared.b16 {%0,%1,%2,%3},[%4];"
                 : "=r"(r0), "=r"(r1), "=r"(r2), "=r"(r3) : "r"(a));
}

__device__ __forceinline__ void ldm_x2(unsigned& r0, unsigned& r1, const void* p)
{
    unsigned a = (unsigned)__cvta_generic_to_shared(p);
    asm volatile("ldmatrix.sync.aligned.m8n8.x2.shared.b16 {%0,%1},[%2];"
                 : "=r"(r0), "=r"(r1) : "r"(a));
}

__device__ __forceinline__ void ldm_x2t(unsigned& r0, unsigned& r1, const void* p)
{
    unsigned a = (unsigned)__cvta_generic_to_shared(p);
    asm volatile("ldmatrix.sync.aligned.m8n8.x2.trans.shared.b16 {%0,%1},[%2];"
                 : "=r"(r0), "=r"(r1) : "r"(a));
}

__device__ __forceinline__ void cp16(void* dst, const void* src)
{
    unsigned d = (unsigned)__cvta_generic_to_shared(dst);
    asm volatile("cp.async.cg.shared.global [%0], [%1], 16;" :: "r"(d), "l"(src));
}
#define CP_COMMIT() asm volatile("cp.async.commit_group;")
#define CP_WAIT0()  asm volatile("cp.async.wait_group 0;")

__device__ __forceinline__ unsigned pack_h2(float x, float y)
{
    __half2 p = __floats2half2_rn(x, y);
    return *(unsigned*)&p;
}

// 16B-chunk XOR swizzle for 64-col fp16 tiles (row*64 elems + chunk^row&7)
__device__ __forceinline__ int swz64(int r, int c8)
{
    return r * 64 + ((c8 ^ (r & 7)) * 8);
}

// ---------------- merged fp32 -> fp16 conversion (single launch) -----------
#define NF4_IN (NELEM >> 2)   // 2^20 float4 per input tensor
#define NF4_W  (WELEM >> 2)   // 2^18 float4 per weight tensor
#define NF4_TOT (3*NF4_IN + 4*NF4_W)

__global__ void split_all(const float* __restrict__ q, const float* __restrict__ k,
                          const float* __restrict__ v, const float* __restrict__ wq,
                          const float* __restrict__ wk, const float* __restrict__ wv,
                          const float* __restrict__ wo)
{
    for (size_t i = blockIdx.x * blockDim.x + threadIdx.x; i < NF4_TOT;
         i += (size_t)gridDim.x * blockDim.x) {
        const float* src;
        __half* h;
        size_t off;
        if (i < 3*NF4_IN) {
            int slot = (int)(i >> 20);
            off = i & (NF4_IN - 1);
            src = (slot == 0) ? q : (slot == 1) ? k : v;
            h = gX + (size_t)slot * NELEM;
        } else {
            size_t j = i - 3*NF4_IN;
            int slot = (int)(j >> 18);
            off = j & (NF4_W - 1);
            src = (slot == 0) ? wq : (slot == 1) ? wk : (slot == 2) ? wv : wo;
            h = gW + (size_t)slot * WELEM;
        }
        float4 val = ((const float4*)src)[off];
        ((uint2*)h)[off] = make_uint2(pack_h2(val.x, val.y),
                                      pack_h2(val.z, val.w));
    }
}

// ---------------- GEMM mainloop body (1-term, term-major order) ------------
#define GEMM_PAIR_BODY1(mp)                                                   \
    {                                                                         \
        unsigned ah[2][4];                                                    \
        _Pragma("unroll")                                                     \
        for (int q = 0; q < 2; q++) {                                         \
            int off = (wm + ((mp)*2 + q) * 16 + ar) * SAPAD + ac;             \
            ldm_x4(ah[q][0], ah[q][1], ah[q][2], ah[q][3], &sA[st][off]);     \
        }                                                                     \
        _Pragma("unroll")                                                     \
        for (int q = 0; q < 2; q++)                                           \
            _Pragma("unroll")                                                 \
            for (int ni = 0; ni < 4; ni++)                                    \
                mma16816h(c[(mp)*2 + q][ni], ah[q][0], ah[q][1], ah[q][2],    \
                          ah[q][3], bf[ni][0], bf[ni][1]);                    \
    }

// ---------------- QKV projection GEMM (1-term fp16) ------------------------
#define SAPAD 24

__global__ __launch_bounds__(256, 2) void gemm_qkv(
    const float* __restrict__ bq, const float* __restrict__ bk,
    const float* __restrict__ bv)
{
    __shared__ __half sA[2][128*SAPAD];
    __shared__ __half sB[2][128*SAPAD];

    const int z = blockIdx.z;
    const __half* Xp = gX + (size_t)z * NELEM;
    const __half* Wp = gW + (size_t)z * WELEM;
    const float* bias = (z == 0) ? bq : (z == 1) ? bk : bv;
    const float scale = (z == 0) ? 0.125f : 1.0f;

    const int tid = threadIdx.x, lane = tid & 31, warp = tid >> 5;
    const int m0 = blockIdx.y * 128, n0 = blockIdx.x * 128;
    const int wm = (warp & 1) * 64, wn = (warp >> 1) * 32;

    const int lrow = tid >> 1, lch = (tid & 1) * 8;
    const __half* gA = Xp + (size_t)(m0 + lrow) * DM + lch;
    const __half* gB = Wp + (size_t)(n0 + lrow) * DM + lch;
    const int so = lrow * SAPAD + lch;

    float c[4][4][4];
    #pragma unroll
    for (int i = 0; i < 4; i++)
        #pragma unroll
        for (int j = 0; j < 4; j++)
            #pragma unroll
            for (int r = 0; r < 4; r++) c[i][j][r] = 0.0f;

    cp16(&sA[0][so], gA);
    cp16(&sB[0][so], gB);
    CP_COMMIT();

    const int ar = lane & 15, ac = (lane >> 4) * 8;
    const int br = lane & 7,  bc = ((lane >> 3) & 1) * 8;

    for (int kt = 0; kt < 64; kt++) {
        const int st = kt & 1;
        CP_WAIT0();
        __syncthreads();
        if (kt < 63) {
            int ko = (kt + 1) * 16;
            cp16(&sA[st ^ 1][so], gA + ko);
            cp16(&sB[st ^ 1][so], gB + ko);
            CP_COMMIT();
        }

        unsigned bf[4][2];
        #pragma unroll
        for (int ni = 0; ni < 4; ni++) {
            int off = (wn + ni * 8 + br) * SAPAD + bc;
            ldm_x2(bf[ni][0], bf[ni][1], &sB[st][off]);
        }
        GEMM_PAIR_BODY1(0)
        GEMM_PAIR_BODY1(1)
    }

    // epilogue: + bias, * scale(Q), convert, scatter to (b,h,n,d)
    const int r0 = lane >> 2, cq = (lane & 3) * 2;
    #pragma unroll
    for (int mi = 0; mi < 4; mi++) {
        #pragma unroll
        for (int ni = 0; ni < 4; ni++) {
            int col = n0 + wn + ni * 8 + cq;
            float b0 = bias[col], b1 = bias[col + 1];
            int hh = col >> 6, d = col & 63;
            #pragma unroll
            for (int half = 0; half < 2; half++) {
                int row = m0 + wm + mi * 16 + r0 + half * 8;
                float v0 = (c[mi][ni][half * 2 + 0] + b0) * scale;
                float v1 = (c[mi][ni][half * 2 + 1] + b1) * scale;
                int bb = row >> 11, n = row & (NSEQ - 1);
                size_t idx = (((size_t)(bb * NH + hh)) * NSEQ + n) * HD + d;
                unsigned pv = pack_h2(v0, v1);
                if (z == 0)      *(unsigned*)&gQ[idx] = pv;
                else if (z == 1) *(unsigned*)&gK[idx] = pv;
                else             *(unsigned*)&gV[idx] = pv;
            }
        }
    }
}

// ---------------- output projection GEMM (1-term fp16) ---------------------
__global__ __launch_bounds__(256, 2) void gemm_out(
    const float* __restrict__ bo, float* __restrict__ out)
{
    __shared__ __half sA[2][128*SAPAD];
    __shared__ __half sB[2][128*SAPAD];

    const __half* Wp = gW + 3 * WELEM;

    const int tid = threadIdx.x, lane = tid & 31, warp = tid >> 5;
    const int m0 = blockIdx.y * 128, n0 = blockIdx.x * 128;
    const int wm = (warp & 1) * 64, wn = (warp >> 1) * 32;

    const int lrow = tid >> 1, lch = (tid & 1) * 8;
    const __half* gA = gO + (size_t)(m0 + lrow) * DM + lch;
    const __half* gB = Wp + (size_t)(n0 + lrow) * DM + lch;
    const int so = lrow * SAPAD + lch;

    float c[4][4][4];
    #pragma unroll
    for (int i = 0; i < 4; i++)
        #pragma unroll
        for (int j = 0; j < 4; j++)
            #pragma unroll
            for (int r = 0; r < 4; r++) c[i][j][r] = 0.0f;

    cp16(&sA[0][so], gA);
    cp16(&sB[0][so], gB);
    CP_COMMIT();

    const int ar = lane & 15, ac = (lane >> 4) * 8;
    const int br = lane & 7,  bc = ((lane >> 3) & 1) * 8;

    for (int kt = 0; kt < 64; kt++) {
        const int st = kt & 1;
        CP_WAIT0();
        __syncthreads();
        if (kt < 63) {
            int ko = (kt + 1) * 16;
            cp16(&sA[st ^ 1][so], gA + ko);
            cp16(&sB[st ^ 1][so], gB + ko);
            CP_COMMIT();
        }

        unsigned bf[4][2];
        #pragma unroll
        for (int ni = 0; ni < 4; ni++) {
            int off = (wn + ni * 8 + br) * SAPAD + bc;
            ldm_x2(bf[ni][0], bf[ni][1], &sB[st][off]);
        }
        GEMM_PAIR_BODY1(0)
        GEMM_PAIR_BODY1(1)
    }

    const int r0 = lane >> 2, cq = (lane & 3) * 2;
    #pragma unroll
    for (int mi = 0; mi < 4; mi++) {
        #pragma unroll
        for (int ni = 0; ni < 4; ni++) {
            int col = n0 + wn + ni * 8 + cq;
            float b0 = bo[col], b1 = bo[col + 1];
            #pragma unroll
            for (int half = 0; half < 2; half++) {
                int row = m0 + wm + mi * 16 + r0 + half * 8;
                float2 v = make_float2(c[mi][ni][half * 2 + 0] + b0,
                                       c[mi][ni][half * 2 + 1] + b1);
                *(float2*)&out[(size_t)row * DM + col] = v;
            }
        }
    }
}

// ---------------- flash attention -------------------------------------------
// S: Q fp16 x K fp16 (1 MMA). PV: P fp16 x V fp16 (1 MMA).
// XOR-swizzled smem: Q 128x64, KV 2 stages x 2 x 64x64. 49,152 B -> 2 CTAs/SM.
#define QTSZ   (128*64)              // elems per Q tile
#define KVTSZ  (64*64)               // elems per K/V tile
#define KVSTG  (2*KVTSZ)             // elems per KV stage [K, V]
#define FLASH_SMEM ((QTSZ + 2*KVSTG) * 2)   // bytes = 49152

__global__ __launch_bounds__(256, 2) void flash()
{
    extern __shared__ __half sm[];
    __half* sQ  = sm;                 // [128x64] swizzled
    __half* sKV = sm + QTSZ;          // [stage][K,V][64x64]

    const int tid = threadIdx.x, lane = tid & 31, warp = tid >> 5;
    const int bh = blockIdx.y, q0 = blockIdx.x * 128;
    const size_t base = (size_t)bh * NSEQ * HD;

    // Q tile: 1024 chunks; 4 per thread
    #pragma unroll
    for (int u = 0; u < 4; u++) {
        int id = tid + u * 256;
        int r = id >> 3, c8 = id & 7;
        cp16(&sQ[swz64(r, c8)], gQ + base + (size_t)(q0 + r) * HD + c8 * 8);
    }
    // KV stage 0: 2 x 512 chunks; 4 per thread
    #pragma unroll
    for (int u = 0; u < 4; u++) {
        int id = tid + u * 256;
        int t = id >> 9, rem = id & 511;
        int r = rem >> 3, c8 = rem & 7;
        size_t g = base + (size_t)r * HD + c8 * 8;
        const void* src = (t == 0) ? (const void*)(gK + g)
                                   : (const void*)(gV + g);
        cp16(&sKV[t * KVTSZ + swz64(r, c8)], src);
    }
    CP_COMMIT();

    float o[8][4];
    #pragma unroll
    for (int i = 0; i < 8; i++)
        #pragma unroll
        for (int j = 0; j < 4; j++) o[i][j] = 0.0f;
    float mr0 = -1e30f, mr1 = -1e30f, lr0 = 0.0f, lr1 = 0.0f;

    const int ar = lane & 15;
    const int achk = lane >> 4;          // A-operand chunk half
    const int br = lane & 7;
    const int bchk = (lane >> 3) & 1;    // B-operand chunk half

    for (int kt = 0; kt < NSEQ / 64; kt++) {
        const int st = kt & 1;
        CP_WAIT0();
        __syncthreads();
        if (kt < NSEQ / 64 - 1) {
            __half* d = sKV + (st ^ 1) * KVSTG;
            size_t kb = base + (size_t)(kt + 1) * 64 * HD;
            #pragma unroll
            for (int u = 0; u < 4; u++) {
                int id = tid + u * 256;
                int t = id >> 9, rem = id & 511;
                int r = rem >> 3, c8 = rem & 7;
                size_t g = kb + (size_t)r * HD + c8 * 8;
                const void* src = (t == 0) ? (const void*)(gK + g)
                                           : (const void*)(gV + g);
                cp16(&d[t * KVTSZ + swz64(r, c8)], src);
            }
            CP_COMMIT();
        }

        const __half* Ks = sKV + st * KVSTG;
        const __half* Vs = Ks + KVTSZ;

        float s[8][4];
        #pragma unroll
        for (int i = 0; i < 8; i++)
            #pragma unroll
            for (int j = 0; j < 4; j++) s[i][j] = 0.0f;

        // S = Q.K^T — 1 term, term-major over ni-quads
        #pragma unroll
        for (int kk = 0; kk < 4; kk++) {
            unsigned ah[4];
            int arow = warp * 16 + ar;
            int aoff = swz64(arow, kk * 2 + achk);
            ldm_x4(ah[0], ah[1], ah[2], ah[3], &sQ[aoff]);
            #pragma unroll
            for (int nh = 0; nh < 2; nh++) {
                unsigned kb4[4][2];
                #pragma unroll
                for (int nq = 0; nq < 4; nq++) {
                    int krow = (nh * 4 + nq) * 8 + br;
                    int koff = swz64(krow, kk * 2 + bchk);
                    ldm_x2(kb4[nq][0], kb4[nq][1], &Ks[koff]);
                }
                #pragma unroll
                for (int nq = 0; nq < 4; nq++)
                    mma16816h(s[nh * 4 + nq], ah[0], ah[1], ah[2], ah[3],
                              kb4[nq][0], kb4[nq][1]);
            }
        }

        float mx0 = -1e30f, mx1 = -1e30f;
        #pragma unroll
        for (int ni = 0; ni < 8; ni++) {
            mx0 = fmaxf(mx0, fmaxf(s[ni][0], s[ni][1]));
            mx1 = fmaxf(mx1, fmaxf(s[ni][2], s[ni][3]));
        }
        mx0 = fmaxf(mx0, __shfl_xor_sync(0xffffffffu, mx0, 1));
        mx0 = fmaxf(mx0, __shfl_xor_sync(0xffffffffu, mx0, 2));
        mx1 = fmaxf(mx1, __shfl_xor_sync(0xffffffffu, mx1, 1));
        mx1 = fmaxf(mx1, __shfl_xor_sync(0xffffffffu, mx1, 2));

        float nm0 = fmaxf(mr0, mx0), nm1 = fmaxf(mr1, mx1);
        float cr0 = __expf(mr0 - nm0), cr1 = __expf(mr1 - nm1);
        mr0 = nm0; mr1 = nm1;

        float sum0 = 0.0f, sum1 = 0.0f;
        #pragma unroll
        for (int ni = 0; ni < 8; ni++) {
            s[ni][0] = __expf(s[ni][0] - nm0);
            s[ni][1] = __expf(s[ni][1] - nm0);
            s[ni][2] = __expf(s[ni][2] - nm1);
            s[ni][3] = __expf(s[ni][3] - nm1);
            sum0 += s[ni][0] + s[ni][1];
            sum1 += s[ni][2] + s[ni][3];
        }
        sum0 += __shfl_xor_sync(0xffffffffu, sum0, 1);
        sum0 += __shfl_xor_sync(0xffffffffu, sum0, 2);
        sum1 += __shfl_xor_sync(0xffffffffu, sum1, 1);
        sum1 += __shfl_xor_sync(0xffffffffu, sum1, 2);
        lr0 = lr0 * cr0 + sum0;
        lr1 = lr1 * cr1 + sum1;
        #pragma unroll
        for (int dj = 0; dj < 8; dj++) {
            o[dj][0] *= cr0; o[dj][1] *= cr0;
            o[dj][2] *= cr1; o[dj][3] *= cr1;
        }

        // O += P(fp16) . V(fp16) — term-major over dj-quads
        #pragma unroll
        for (int kk = 0; kk < 4; kk++) {
            unsigned p0 = pack_h2(s[2*kk][0],   s[2*kk][1]);
            unsigned p1 = pack_h2(s[2*kk][2],   s[2*kk][3]);
            unsigned p2 = pack_h2(s[2*kk+1][0], s[2*kk+1][1]);
            unsigned p3 = pack_h2(s[2*kk+1][2], s[2*kk+1][3]);
            int vrow = kk * 16 + ar;
            #pragma unroll
            for (int dh = 0; dh < 2; dh++) {
                unsigned vb4[4][2];
                #pragma unroll
                for (int dq = 0; dq < 4; dq++) {
                    int voff = swz64(vrow, dh * 4 + dq);
                    ldm_x2t(vb4[dq][0], vb4[dq][1], &Vs[voff]);
                }
                #pragma unroll
                for (int dq = 0; dq < 4; dq++)
                    mma16816h(o[dh * 4 + dq], p0, p1, p2, p3,
                              vb4[dq][0], vb4[dq][1]);
            }
        }
    }

    const int b = bh >> 4, h = bh & 15;
    const int row0 = q0 + warp * 16 + (lane >> 2);
    const float inv0 = 1.0f / lr0, inv1 = 1.0f / lr1;
    const size_t rb = ((size_t)(b * NSEQ) + row0) * DM + h * HD;
    #pragma unroll
    for (int dj = 0; dj < 8; dj++) {
        int d = dj * 8 + (lane & 3) * 2;
        *(unsigned*)&gO[rb + d] = pack_h2(o[dj][0] * inv0, o[dj][1] * inv0);
        *(unsigned*)&gO[rb + (size_t)8 * DM + d] =
            pack_h2(o[dj][2] * inv1, o[dj][3] * inv1);
    }
}

// ---------------------------------------------------------------------------
extern "C" void kernel_launch(void* const* d_in, const int* in_sizes, int n_in,
                              void* d_out, int out_size)
{
    (void)in_sizes; (void)n_in; (void)out_size;
    const float* queries = (const float*)d_in[0];
    const float* keys    = (const float*)d_in[1];
    const float* values  = (const float*)d_in[2];
    const float* Wq = (const float*)d_in[3];
    const float* bq = (const float*)d_in[4];
    const float* Wk = (const float*)d_in[5];
    const float* bk = (const float*)d_in[6];
    const float* Wv = (const float*)d_in[7];
    const float* bv = (const float*)d_in[8];
    const float* Wo = (const float*)d_in[9];
    const float* bo = (const float*)d_in[10];
    float* out = (float*)d_out;

    cudaFuncSetAttribute(flash, cudaFuncAttributeMaxDynamicSharedMemorySize,
                         FLASH_SMEM);

    // fp32 -> fp16 (single launch)
    split_all<<<2048, 256>>>(queries, keys, values, Wq, Wk, Wv, Wo);

    // QKV projections
    gemm_qkv<<<dim3(DM / 128, MROWS / 128, 3), 256>>>(bq, bk, bv);

    // attention
    flash<<<dim3(NSEQ / 128, NB * NH), 256, FLASH_SMEM>>>();

    // output projection
    gemm_out<<<dim3(DM / 128, MROWS / 128), 256>>>(bo, out);
}

// round 11
// speedup vs baseline: 2.2652x; 1.0549x over previous
#include <cuda_runtime.h>
#include <cuda_bf16.h>
#include <cuda_fp16.h>
#include <math.h>
#include <stdint.h>

#define DM   1024
#define NSEQ 2048
#define NB   2
#define NH   16
#define HD   64
#define MROWS (NB*NSEQ)          // 4096
#define NELEM ((size_t)MROWS*DM) // 4,194,304
#define WELEM ((size_t)DM*DM)    // 1,048,576

// ---------------- scratch (__device__ globals; no allocations) -------------
__device__ __half gX[3*NELEM];                // inputs q,k,v single fp16
__device__ __half gW[4*WELEM];                // weights single fp16
__device__ __half gQ[NELEM];                  // (b,h,n,d), Q pre-scaled
__device__ __half gK[NELEM];                  // K single fp16
__device__ __half gV[NELEM];                  // V single fp16
__device__ __half gO[NELEM];                  // attn out (b*n, h*d), single

// ---------------- PTX helpers ---------------------------------------------
__device__ __forceinline__ void mma16816h(float* c,
    unsigned a0, unsigned a1, unsigned a2, unsigned a3,
    unsigned b0, unsigned b1)
{
    asm volatile(
        "mma.sync.aligned.m16n8k16.row.col.f32.f16.f16.f32 "
        "{%0,%1,%2,%3},{%4,%5,%6,%7},{%8,%9},{%0,%1,%2,%3};"
        : "+f"(c[0]), "+f"(c[1]), "+f"(c[2]), "+f"(c[3])
        : "r"(a0), "r"(a1), "r"(a2), "r"(a3), "r"(b0), "r"(b1));
}

__device__ __forceinline__ void ldm_x4(unsigned& r0, unsigned& r1,
                                       unsigned& r2, unsigned& r3,
                                       const void* p)
{
    unsigned a = (unsigned)__cvta_generic_to_shared(p);
    asm volatile("ldmatrix.sync.aligned.m8n8.x4.shared.b16 {%0,%1,%2,%3},[%4];"
                 : "=r"(r0), "=r"(r1), "=r"(r2), "=r"(r3) : "r"(a));
}

__device__ __forceinline__ void ldm_x2(unsigned& r0, unsigned& r1, const void* p)
{
    unsigned a = (unsigned)__cvta_generic_to_shared(p);
    asm volatile("ldmatrix.sync.aligned.m8n8.x2.shared.b16 {%0,%1},[%2];"
                 : "=r"(r0), "=r"(r1) : "r"(a));
}

__device__ __forceinline__ void ldm_x2t(unsigned& r0, unsigned& r1, const void* p)
{
    unsigned a = (unsigned)__cvta_generic_to_shared(p);
    asm volatile("ldmatrix.sync.aligned.m8n8.x2.trans.shared.b16 {%0,%1},[%2];"
                 : "=r"(r0), "=r"(r1) : "r"(a));
}

__device__ __forceinline__ void cp16(void* dst, const void* src)
{
    unsigned d = (unsigned)__cvta_generic_to_shared(dst);
    asm volatile("cp.async.cg.shared.global [%0], [%1], 16;" :: "r"(d), "l"(src));
}
#define CP_COMMIT() asm volatile("cp.async.commit_group;")
#define CP_WAIT0()  asm volatile("cp.async.wait_group 0;")

__device__ __forceinline__ unsigned pack_h2(float x, float y)
{
    __half2 p = __floats2half2_rn(x, y);
    return *(unsigned*)&p;
}

// 16B-chunk XOR swizzle for 64-col fp16 tiles (row*64 elems + chunk^row&7)
__device__ __forceinline__ int swz64(int r, int c8)
{
    return r * 64 + ((c8 ^ (r & 7)) * 8);
}

// ---------------- merged fp32 -> fp16 conversion (single launch) -----------
#define NF4_IN (NELEM >> 2)   // 2^20 float4 per input tensor
#define NF4_W  (WELEM >> 2)   // 2^18 float4 per weight tensor
#define NF4_TOT (3*NF4_IN + 4*NF4_W)

__global__ void split_all(const float* __restrict__ q, const float* __restrict__ k,
                          const float* __restrict__ v, const float* __restrict__ wq,
                          const float* __restrict__ wk, const float* __restrict__ wv,
                          const float* __restrict__ wo)
{
    for (size_t i = blockIdx.x * blockDim.x + threadIdx.x; i < NF4_TOT;
         i += (size_t)gridDim.x * blockDim.x) {
        const float* src;
        __half* h;
        size_t off;
        if (i < 3*NF4_IN) {
            int slot = (int)(i >> 20);
            off = i & (NF4_IN - 1);
            src = (slot == 0) ? q : (slot == 1) ? k : v;
            h = gX + (size_t)slot * NELEM;
        } else {
            size_t j = i - 3*NF4_IN;
            int slot = (int)(j >> 18);
            off = j & (NF4_W - 1);
            src = (slot == 0) ? wq : (slot == 1) ? wk : (slot == 2) ? wv : wo;
            h = gW + (size_t)slot * WELEM;
        }
        float4 val = ((const float4*)src)[off];
        ((uint2*)h)[off] = make_uint2(pack_h2(val.x, val.y),
                                      pack_h2(val.z, val.w));
    }
}

// ---------------- GEMM mainloop body (BK=32: two k-steps per call) ---------
// SAPAD2 = 40 fp16 (80B rows = 5 x 16B chunks, odd -> conflict-free ldmatrix)
#define SAPAD2 40

#define GEMM_KSTEP(ks)                                                        \
    {                                                                         \
        unsigned bf[4][2];                                                    \
        _Pragma("unroll")                                                     \
        for (int ni = 0; ni < 4; ni++) {                                      \
            int off = (wn + ni * 8 + br) * SAPAD2 + (ks) * 16 + bc;           \
            ldm_x2(bf[ni][0], bf[ni][1], &sB[st][off]);                       \
        }                                                                     \
        _Pragma("unroll")                                                     \
        for (int mp = 0; mp < 2; mp++) {                                      \
            unsigned ah[2][4];                                                \
            _Pragma("unroll")                                                 \
            for (int q = 0; q < 2; q++) {                                     \
                int off = (wm + (mp * 2 + q) * 16 + ar) * SAPAD2              \
                          + (ks) * 16 + ac;                                   \
                ldm_x4(ah[q][0], ah[q][1], ah[q][2], ah[q][3], &sA[st][off]); \
            }                                                                 \
            _Pragma("unroll")                                                 \
            for (int q = 0; q < 2; q++)                                       \
                _Pragma("unroll")                                             \
                for (int ni = 0; ni < 4; ni++)                                \
                    mma16816h(c[mp * 2 + q][ni], ah[q][0], ah[q][1],          \
                              ah[q][2], ah[q][3], bf[ni][0], bf[ni][1]);      \
        }                                                                     \
    }

// stage loader: A,B tiles of 128 rows x 32 fp16; 1024 chunks, 4 per thread
#define GEMM_LOAD_STAGE(dstA, dstB, koff)                                     \
    {                                                                         \
        _Pragma("unroll")                                                     \
        for (int u = 0; u < 2; u++) {                                         \
            int id = tid + u * 256;                                           \
            int r = id >> 2, c4 = (id & 3) * 8;                               \
            cp16(&(dstA)[r * SAPAD2 + c4],                                    \
                 gA + (size_t)r * DM + (koff) + c4);                          \
            cp16(&(dstB)[r * SAPAD2 + c4],                                    \
                 gB + (size_t)r * DM + (koff) + c4);                          \
        }                                                                     \
    }

// ---------------- QKV projection GEMM (1-term fp16, BK=32) -----------------
__global__ __launch_bounds__(256, 2) void gemm_qkv(
    const float* __restrict__ bq, const float* __restrict__ bk,
    const float* __restrict__ bv)
{
    __shared__ __half sA[2][128*SAPAD2];
    __shared__ __half sB[2][128*SAPAD2];

    const int z = blockIdx.z;
    const __half* Xp = gX + (size_t)z * NELEM;
    const __half* Wp = gW + (size_t)z * WELEM;
    const float* bias = (z == 0) ? bq : (z == 1) ? bk : bv;
    const float scale = (z == 0) ? 0.125f : 1.0f;

    const int tid = threadIdx.x, lane = tid & 31, warp = tid >> 5;
    const int m0 = blockIdx.y * 128, n0 = blockIdx.x * 128;
    const int wm = (warp & 1) * 64, wn = (warp >> 1) * 32;

    const __half* gA = Xp + (size_t)m0 * DM;
    const __half* gB = Wp + (size_t)n0 * DM;

    float c[4][4][4];
    #pragma unroll
    for (int i = 0; i < 4; i++)
        #pragma unroll
        for (int j = 0; j < 4; j++)
            #pragma unroll
            for (int r = 0; r < 4; r++) c[i][j][r] = 0.0f;

    GEMM_LOAD_STAGE(sA[0], sB[0], 0)
    CP_COMMIT();

    const int ar = lane & 15, ac = (lane >> 4) * 8;
    const int br = lane & 7,  bc = ((lane >> 3) & 1) * 8;

    for (int kt = 0; kt < 32; kt++) {
        const int st = kt & 1;
        CP_WAIT0();
        __syncthreads();
        if (kt < 31) {
            GEMM_LOAD_STAGE(sA[st ^ 1], sB[st ^ 1], (kt + 1) * 32)
            CP_COMMIT();
        }
        GEMM_KSTEP(0)
        GEMM_KSTEP(1)
    }

    // epilogue: + bias, * scale(Q), convert, scatter to (b,h,n,d)
    const int r0 = lane >> 2, cq = (lane & 3) * 2;
    #pragma unroll
    for (int mi = 0; mi < 4; mi++) {
        #pragma unroll
        for (int ni = 0; ni < 4; ni++) {
            int col = n0 + wn + ni * 8 + cq;
            float b0 = bias[col], b1 = bias[col + 1];
            int hh = col >> 6, d = col & 63;
            #pragma unroll
            for (int half = 0; half < 2; half++) {
                int row = m0 + wm + mi * 16 + r0 + half * 8;
                float v0 = (c[mi][ni][half * 2 + 0] + b0) * scale;
                float v1 = (c[mi][ni][half * 2 + 1] + b1) * scale;
                int bb = row >> 11, n = row & (NSEQ - 1);
                size_t idx = (((size_t)(bb * NH + hh)) * NSEQ + n) * HD + d;
                unsigned pv = pack_h2(v0, v1);
                if (z == 0)      *(unsigned*)&gQ[idx] = pv;
                else if (z == 1) *(unsigned*)&gK[idx] = pv;
                else             *(unsigned*)&gV[idx] = pv;
            }
        }
    }
}

// ---------------- output projection GEMM (1-term fp16, BK=32) --------------
__global__ __launch_bounds__(256, 2) void gemm_out(
    const float* __restrict__ bo, float* __restrict__ out)
{
    __shared__ __half sA[2][128*SAPAD2];
    __shared__ __half sB[2][128*SAPAD2];

    const __half* Wp = gW + 3 * WELEM;

    const int tid = threadIdx.x, lane = tid & 31, warp = tid >> 5;
    const int m0 = blockIdx.y * 128, n0 = blockIdx.x * 128;
    const int wm = (warp & 1) * 64, wn = (warp >> 1) * 32;

    const __half* gA = gO + (size_t)m0 * DM;
    const __half* gB = Wp + (size_t)n0 * DM;

    float c[4][4][4];
    #pragma unroll
    for (int i = 0; i < 4; i++)
        #pragma unroll
        for (int j = 0; j < 4; j++)
            #pragma unroll
            for (int r = 0; r < 4; r++) c[i][j][r] = 0.0f;

    GEMM_LOAD_STAGE(sA[0], sB[0], 0)
    CP_COMMIT();

    const int ar = lane & 15, ac = (lane >> 4) * 8;
    const int br = lane & 7,  bc = ((lane >> 3) & 1) * 8;

    for (int kt = 0; kt < 32; kt++) {
        const int st = kt & 1;
        CP_WAIT0();
        __syncthreads();
        if (kt < 31) {
            GEMM_LOAD_STAGE(sA[st ^ 1], sB[st ^ 1], (kt + 1) * 32)
            CP_COMMIT();
        }
        GEMM_KSTEP(0)
        GEMM_KSTEP(1)
    }

    const int r0 = lane >> 2, cq = (lane & 3) * 2;
    #pragma unroll
    for (int mi = 0; mi < 4; mi++) {
        #pragma unroll
        for (int ni = 0; ni < 4; ni++) {
            int col = n0 + wn + ni * 8 + cq;
            float b0 = bo[col], b1 = bo[col + 1];
            #pragma unroll
            for (int half = 0; half < 2; half++) {
                int row = m0 + wm + mi * 16 + r0 + half * 8;
                float2 v = make_float2(c[mi][ni][half * 2 + 0] + b0,
                                       c[mi][ni][half * 2 + 1] + b1);
                *(float2*)&out[(size_t)row * DM + col] = v;
            }
        }
    }
}

// ---------------- flash attention -------------------------------------------
// S: Q fp16 x K fp16 (1 MMA). PV: P fp16 x V fp16 (1 MMA).
// XOR-swizzled smem: Q 128x64, KV 2 stages x 2 x 64x64. 49,152 B -> 2 CTAs/SM.
#define QTSZ   (128*64)              // elems per Q tile
#define KVTSZ  (64*64)               // elems per K/V tile
#define KVSTG  (2*KVTSZ)             // elems per KV stage [K, V]
#define FLASH_SMEM ((QTSZ + 2*KVSTG) * 2)   // bytes = 49152

__global__ __launch_bounds__(256, 2) void flash()
{
    extern __shared__ __half sm[];
    __half* sQ  = sm;                 // [128x64] swizzled
    __half* sKV = sm + QTSZ;          // [stage][K,V][64x64]

    const int tid = threadIdx.x, lane = tid & 31, warp = tid >> 5;
    const int bh = blockIdx.y, q0 = blockIdx.x * 128;
    const size_t base = (size_t)bh * NSEQ * HD;

    // Q tile: 1024 chunks; 4 per thread
    #pragma unroll
    for (int u = 0; u < 4; u++) {
        int id = tid + u * 256;
        int r = id >> 3, c8 = id & 7;
        cp16(&sQ[swz64(r, c8)], gQ + base + (size_t)(q0 + r) * HD + c8 * 8);
    }
    // KV stage 0: 2 x 512 chunks; 4 per thread
    #pragma unroll
    for (int u = 0; u < 4; u++) {
        int id = tid + u * 256;
        int t = id >> 9, rem = id & 511;
        int r = rem >> 3, c8 = rem & 7;
        size_t g = base + (size_t)r * HD + c8 * 8;
        const void* src = (t == 0) ? (const void*)(gK + g)
                                   : (const void*)(gV + g);
        cp16(&sKV[t * KVTSZ + swz64(r, c8)], src);
    }
    CP_COMMIT();

    float o[8][4];
    #pragma unroll
    for (int i = 0; i < 8; i++)
        #pragma unroll
        for (int j = 0; j < 4; j++) o[i][j] = 0.0f;
    float mr0 = -1e30f, mr1 = -1e30f, lr0 = 0.0f, lr1 = 0.0f;

    const int ar = lane & 15;
    const int achk = lane >> 4;          // A-operand chunk half
    const int br = lane & 7;
    const int bchk = (lane >> 3) & 1;    // B-operand chunk half

    for (int kt = 0; kt < NSEQ / 64; kt++) {
        const int st = kt & 1;
        CP_WAIT0();
        __syncthreads();
        if (kt < NSEQ / 64 - 1) {
            __half* d = sKV + (st ^ 1) * KVSTG;
            size_t kb = base + (size_t)(kt + 1) * 64 * HD;
            #pragma unroll
            for (int u = 0; u < 4; u++) {
                int id = tid + u * 256;
                int t = id >> 9, rem = id & 511;
                int r = rem >> 3, c8 = rem & 7;
                size_t g = kb + (size_t)r * HD + c8 * 8;
                const void* src = (t == 0) ? (const void*)(gK + g)
                                           : (const void*)(gV + g);
                cp16(&d[t * KVTSZ + swz64(r, c8)], src);
            }
            CP_COMMIT();
        }

        const __half* Ks = sKV + st * KVSTG;
        const __half* Vs = Ks + KVTSZ;

        float s[8][4];
        #pragma unroll
        for (int i = 0; i < 8; i++)
            #pragma unroll
            for (int j = 0; j < 4; j++) s[i][j] = 0.0f;

        // S = Q.K^T — 1 term, term-major over ni-quads
        #pragma unroll
        for (int kk = 0; kk < 4; kk++) {
            unsigned ah[4];
            int arow = warp * 16 + ar;
            int aoff = swz64(arow, kk * 2 + achk);
            ldm_x4(ah[0], ah[1], ah[2], ah[3], &sQ[aoff]);
            #pragma unroll
            for (int nh = 0; nh < 2; nh++) {
                unsigned kb4[4][2];
                #pragma unroll
                for (int nq = 0; nq < 4; nq++) {
                    int krow = (nh * 4 + nq) * 8 + br;
                    int koff = swz64(krow, kk * 2 + bchk);
                    ldm_x2(kb4[nq][0], kb4[nq][1], &Ks[koff]);
                }
                #pragma unroll
                for (int nq = 0; nq < 4; nq++)
                    mma16816h(s[nh * 4 + nq], ah[0], ah[1], ah[2], ah[3],
                              kb4[nq][0], kb4[nq][1]);
            }
        }

        float mx0 = -1e30f, mx1 = -1e30f;
        #pragma unroll
        for (int ni = 0; ni < 8; ni++) {
            mx0 = fmaxf(mx0, fmaxf(s[ni][0], s[ni][1]));
            mx1 = fmaxf(mx1, fmaxf(s[ni][2], s[ni][3]));
        }
        mx0 = fmaxf(mx0, __shfl_xor_sync(0xffffffffu, mx0, 1));
        mx0 = fmaxf(mx0, __shfl_xor_sync(0xffffffffu, mx0, 2));
        mx1 = fmaxf(mx1, __shfl_xor_sync(0xffffffffu, mx1, 1));
        mx1 = fmaxf(mx1, __shfl_xor_sync(0xffffffffu, mx1, 2));

        float nm0 = fmaxf(mr0, mx0), nm1 = fmaxf(mr1, mx1);
        float cr0 = __expf(mr0 - nm0), cr1 = __expf(mr1 - nm1);
        mr0 = nm0; mr1 = nm1;

        float sum0 = 0.0f, sum1 = 0.0f;
        #pragma unroll
        for (int ni = 0; ni < 8; ni++) {
            s[ni][0] = __expf(s[ni][0] - nm0);
            s[ni][1] = __expf(s[ni][1] - nm0);
            s[ni][2] = __expf(s[ni][2] - nm1);
            s[ni][3] = __expf(s[ni][3] - nm1);
            sum0 += s[ni][0] + s[ni][1];
            sum1 += s[ni][2] + s[ni][3];
        }
        sum0 += __shfl_xor_sync(0xffffffffu, sum0, 1);
        sum0 += __shfl_xor_sync(0xffffffffu, sum0, 2);
        sum1 += __shfl_xor_sync(0xffffffffu, sum1, 1);
        sum1 += __shfl_xor_sync(0xffffffffu, sum1, 2);
        lr0 = lr0 * cr0 + sum0;
        lr1 = lr1 * cr1 + sum1;
        #pragma unroll
        for (int dj = 0; dj < 8; dj++) {
            o[dj][0] *= cr0; o[dj][1] *= cr0;
            o[dj][2] *= cr1; o[dj][3] *= cr1;
        }

        // O += P(fp16) . V(fp16) — term-major over dj-quads
        #pragma unroll
        for (int kk = 0; kk < 4; kk++) {
            unsigned p0 = pack_h2(s[2*kk][0],   s[2*kk][1]);
            unsigned p1 = pack_h2(s[2*kk][2],   s[2*kk][3]);
            unsigned p2 = pack_h2(s[2*kk+1][0], s[2*kk+1][1]);
            unsigned p3 = pack_h2(s[2*kk+1][2], s[2*kk+1][3]);
            int vrow = kk * 16 + ar;
            #pragma unroll
            for (int dh = 0; dh < 2; dh++) {
                unsigned vb4[4][2];
                #pragma unroll
                for (int dq = 0; dq < 4; dq++) {
                    int voff = swz64(vrow, dh * 4 + dq);
                    ldm_x2t(vb4[dq][0], vb4[dq][1], &Vs[voff]);
                }
                #pragma unroll
                for (int dq = 0; dq < 4; dq++)
                    mma16816h(o[dh * 4 + dq], p0, p1, p2, p3,
                              vb4[dq][0], vb4[dq][1]);
            }
        }
    }

    const int b = bh >> 4, h = bh & 15;
    const int row0 = q0 + warp * 16 + (lane >> 2);
    const float inv0 = 1.0f / lr0, inv1 = 1.0f / lr1;
    const size_t rb = ((size_t)(b * NSEQ) + row0) * DM + h * HD;
    #pragma unroll
    for (int dj = 0; dj < 8; dj++) {
        int d = dj * 8 + (lane & 3) * 2;
        *(unsigned*)&gO[rb + d] = pack_h2(o[dj][0] * inv0, o[dj][1] * inv0);
        *(unsigned*)&gO[rb + (size_t)8 * DM + d] =
            pack_h2(o[dj][2] * inv1, o[dj][3] * inv1);
    }
}

// ---------------------------------------------------------------------------
extern "C" void kernel_launch(void* const* d_in, const int* in_sizes, int n_in,
                              void* d_out, int out_size)
{
    (void)in_sizes; (void)n_in; (void)out_size;
    const float* queries = (const float*)d_in[0];
    const float* keys    = (const float*)d_in[1];
    const float* values  = (const float*)d_in[2];
    const float* Wq = (const float*)d_in[3];
    const float* bq = (const float*)d_in[4];
    const float* Wk = (const float*)d_in[5];
    const float* bk = (const float*)d_in[6];
    const float* Wv = (const float*)d_in[7];
    const float* bv = (const float*)d_in[8];
    const float* Wo = (const float*)d_in[9];
    const float* bo = (const float*)d_in[10];
    float* out = (float*)d_out;

    cudaFuncSetAttribute(flash, cudaFuncAttributeMaxDynamicSharedMemorySize,
                         FLASH_SMEM);

    // fp32 -> fp16 (single launch)
    split_all<<<2048, 256>>>(queries, keys, values, Wq, Wk, Wv, Wo);

    // QKV projections
    gemm_qkv<<<dim3(DM / 128, MROWS / 128, 3), 256>>>(bq, bk, bv);

    // attention
    flash<<<dim3(NSEQ / 128, NB * NH), 256, FLASH_SMEM>>>();

    // output projection
    gemm_out<<<dim3(DM / 128, MROWS / 128), 256>>>(bo, out);
}

// round 12
// speedup vs baseline: 2.6139x; 1.1539x over previous
#include <cuda_runtime.h>
#include <cuda_bf16.h>
#include <cuda_fp16.h>
#include <math.h>
#include <stdint.h>

#define DM   1024
#define NSEQ 2048
#define NB   2
#define NH   16
#define HD   64
#define MROWS (NB*NSEQ)          // 4096
#define NELEM ((size_t)MROWS*DM) // 4,194,304
#define WELEM ((size_t)DM*DM)    // 1,048,576

// ---------------- scratch (__device__ globals; no allocations) -------------
__device__ __half gX[3*NELEM];                // inputs q,k,v single fp16
__device__ __half gW[4*WELEM];                // weights single fp16
__device__ __half gQ[NELEM];                  // (b,h,n,d), Q pre-scaled
__device__ __half gK[NELEM];                  // K single fp16
__device__ __half gV[NELEM];                  // V single fp16
__device__ __half gO[NELEM];                  // attn out (b*n, h*d), single

// ---------------- PTX helpers ---------------------------------------------
__device__ __forceinline__ void mma16816h(float* c,
    unsigned a0, unsigned a1, unsigned a2, unsigned a3,
    unsigned b0, unsigned b1)
{
    asm volatile(
        "mma.sync.aligned.m16n8k16.row.col.f32.f16.f16.f32 "
        "{%0,%1,%2,%3},{%4,%5,%6,%7},{%8,%9},{%0,%1,%2,%3};"
        : "+f"(c[0]), "+f"(c[1]), "+f"(c[2]), "+f"(c[3])
        : "r"(a0), "r"(a1), "r"(a2), "r"(a3), "r"(b0), "r"(b1));
}

__device__ __forceinline__ void ldm_x4(unsigned& r0, unsigned& r1,
                                       unsigned& r2, unsigned& r3,
                                       const void* p)
{
    unsigned a = (unsigned)__cvta_generic_to_shared(p);
    asm volatile("ldmatrix.sync.aligned.m8n8.x4.shared.b16 {%0,%1,%2,%3},[%4];"
                 : "=r"(r0), "=r"(r1), "=r"(r2), "=r"(r3) : "r"(a));
}

__device__ __forceinline__ void ldm_x2(unsigned& r0, unsigned& r1, const void* p)
{
    unsigned a = (unsigned)__cvta_generic_to_shared(p);
    asm volatile("ldmatrix.sync.aligned.m8n8.x2.shared.b16 {%0,%1},[%2];"
                 : "=r"(r0), "=r"(r1) : "r"(a));
}

__device__ __forceinline__ void ldm_x2t(unsigned& r0, unsigned& r1, const void* p)
{
    unsigned a = (unsigned)__cvta_generic_to_shared(p);
    asm volatile("ldmatrix.sync.aligned.m8n8.x2.trans.shared.b16 {%0,%1},[%2];"
                 : "=r"(r0), "=r"(r1) : "r"(a));
}

__device__ __forceinline__ void cp16(void* dst, const void* src)
{
    unsigned d = (unsigned)__cvta_generic_to_shared(dst);
    asm volatile("cp.async.cg.shared.global [%0], [%1], 16;" :: "r"(d), "l"(src));
}
#define CP_COMMIT() asm volatile("cp.async.commit_group;")
#define CP_WAIT0()  asm volatile("cp.async.wait_group 0;")

__device__ __forceinline__ unsigned pack_h2(float x, float y)
{
    __half2 p = __floats2half2_rn(x, y);
    return *(unsigned*)&p;
}

// 16B-chunk XOR swizzle for 64-col fp16 tiles (row*64 elems + chunk^row&7)
__device__ __forceinline__ int swz64(int r, int c8)
{
    return r * 64 + ((c8 ^ (r & 7)) * 8);
}

// ---------------- merged fp32 -> fp16 conversion (single launch) -----------
#define NF4_IN (NELEM >> 2)   // 2^20 float4 per input tensor
#define NF4_W  (WELEM >> 2)   // 2^18 float4 per weight tensor
#define NF4_TOT (3*NF4_IN + 4*NF4_W)

__global__ void split_all(const float* __restrict__ q, const float* __restrict__ k,
                          const float* __restrict__ v, const float* __restrict__ wq,
                          const float* __restrict__ wk, const float* __restrict__ wv,
                          const float* __restrict__ wo)
{
    for (size_t i = blockIdx.x * blockDim.x + threadIdx.x; i < NF4_TOT;
         i += (size_t)gridDim.x * blockDim.x) {
        const float* src;
        __half* h;
        size_t off;
        if (i < 3*NF4_IN) {
            int slot = (int)(i >> 20);
            off = i & (NF4_IN - 1);
            src = (slot == 0) ? q : (slot == 1) ? k : v;
            h = gX + (size_t)slot * NELEM;
        } else {
            size_t j = i - 3*NF4_IN;
            int slot = (int)(j >> 18);
            off = j & (NF4_W - 1);
            src = (slot == 0) ? wq : (slot == 1) ? wk : (slot == 2) ? wv : wo;
            h = gW + (size_t)slot * WELEM;
        }
        float4 val = ((const float4*)src)[off];
        ((uint2*)h)[off] = make_uint2(pack_h2(val.x, val.y),
                                      pack_h2(val.z, val.w));
    }
}

// ---------------- GEMM: BK=64, swizzled 64-col tiles, dynamic smem ---------
// Layout: sA/sB = [stage][128*64] fp16, swz64 addressing.
#define GTILE   (128*64)                 // elems per tile
#define GSMEM   (4*GTILE*2)              // bytes = 65536 (2 stages x 2 tiles)

// stage load: A,B tiles 128 rows x 8 chunks; 2048 chunks total, 8 per thread
#define GEMM_LOAD_STAGE64(dstA, dstB, koff)                                   \
    {                                                                         \
        _Pragma("unroll")                                                     \
        for (int u = 0; u < 4; u++) {                                         \
            int id = tid + u * 256;                                           \
            int r = id >> 3, c8 = id & 7;                                     \
            int sw = swz64(r, c8);                                            \
            cp16(&(dstA)[sw], gA + (size_t)r * DM + (koff) + c8 * 8);         \
            cp16(&(dstB)[sw], gB + (size_t)r * DM + (koff) + c8 * 8);         \
        }                                                                     \
    }

// one k-step (16 wide) = 16 MMAs; kk in 0..3
#define GEMM_KSTEP64(kk)                                                      \
    {                                                                         \
        unsigned bf[4][2];                                                    \
        _Pragma("unroll")                                                     \
        for (int ni = 0; ni < 4; ni++) {                                      \
            int off = swz64(wn + ni * 8 + br, (kk) * 2 + bchk);               \
            ldm_x2(bf[ni][0], bf[ni][1], &sB[st * GTILE + off]);              \
        }                                                                     \
        _Pragma("unroll")                                                     \
        for (int mp = 0; mp < 2; mp++) {                                      \
            unsigned ah[2][4];                                                \
            _Pragma("unroll")                                                 \
            for (int q = 0; q < 2; q++) {                                     \
                int off = swz64(wm + (mp * 2 + q) * 16 + ar, (kk) * 2 + achk);\
                ldm_x4(ah[q][0], ah[q][1], ah[q][2], ah[q][3],                \
                       &sA[st * GTILE + off]);                                \
            }                                                                 \
            _Pragma("unroll")                                                 \
            for (int q = 0; q < 2; q++)                                       \
                _Pragma("unroll")                                             \
                for (int ni = 0; ni < 4; ni++)                                \
                    mma16816h(c[mp * 2 + q][ni], ah[q][0], ah[q][1],          \
                              ah[q][2], ah[q][3], bf[ni][0], bf[ni][1]);      \
        }                                                                     \
    }

// ---------------- QKV projection GEMM (1-term fp16, BK=64) -----------------
__global__ __launch_bounds__(256, 2) void gemm_qkv(
    const float* __restrict__ bq, const float* __restrict__ bk,
    const float* __restrict__ bv)
{
    extern __shared__ __half gsm[];
    __half* sA = gsm;                // [2][GTILE]
    __half* sB = gsm + 2 * GTILE;    // [2][GTILE]

    const int z = blockIdx.z;
    const __half* Xp = gX + (size_t)z * NELEM;
    const __half* Wp = gW + (size_t)z * WELEM;
    const float* bias = (z == 0) ? bq : (z == 1) ? bk : bv;
    const float scale = (z == 0) ? 0.125f : 1.0f;

    const int tid = threadIdx.x, lane = tid & 31, warp = tid >> 5;
    const int m0 = blockIdx.y * 128, n0 = blockIdx.x * 128;
    const int wm = (warp & 1) * 64, wn = (warp >> 1) * 32;

    const __half* gA = Xp + (size_t)m0 * DM;
    const __half* gB = Wp + (size_t)n0 * DM;

    float c[4][4][4];
    #pragma unroll
    for (int i = 0; i < 4; i++)
        #pragma unroll
        for (int j = 0; j < 4; j++)
            #pragma unroll
            for (int r = 0; r < 4; r++) c[i][j][r] = 0.0f;

    GEMM_LOAD_STAGE64(sA, sB, 0)
    CP_COMMIT();

    const int ar = lane & 15, achk = lane >> 4;
    const int br = lane & 7,  bchk = (lane >> 3) & 1;

    for (int kt = 0; kt < 16; kt++) {
        const int st = kt & 1;
        CP_WAIT0();
        __syncthreads();
        if (kt < 15) {
            GEMM_LOAD_STAGE64(sA + (st ^ 1) * GTILE, sB + (st ^ 1) * GTILE,
                              (kt + 1) * 64)
            CP_COMMIT();
        }
        GEMM_KSTEP64(0)
        GEMM_KSTEP64(1)
        GEMM_KSTEP64(2)
        GEMM_KSTEP64(3)
    }

    // epilogue: + bias, * scale(Q), convert, scatter to (b,h,n,d)
    const int r0 = lane >> 2, cq = (lane & 3) * 2;
    #pragma unroll
    for (int mi = 0; mi < 4; mi++) {
        #pragma unroll
        for (int ni = 0; ni < 4; ni++) {
            int col = n0 + wn + ni * 8 + cq;
            float b0 = bias[col], b1 = bias[col + 1];
            int hh = col >> 6, d = col & 63;
            #pragma unroll
            for (int half = 0; half < 2; half++) {
                int row = m0 + wm + mi * 16 + r0 + half * 8;
                float v0 = (c[mi][ni][half * 2 + 0] + b0) * scale;
                float v1 = (c[mi][ni][half * 2 + 1] + b1) * scale;
                int bb = row >> 11, n = row & (NSEQ - 1);
                size_t idx = (((size_t)(bb * NH + hh)) * NSEQ + n) * HD + d;
                unsigned pv = pack_h2(v0, v1);
                if (z == 0)      *(unsigned*)&gQ[idx] = pv;
                else if (z == 1) *(unsigned*)&gK[idx] = pv;
                else             *(unsigned*)&gV[idx] = pv;
            }
        }
    }
}

// ---------------- output projection GEMM (1-term fp16, BK=64) --------------
__global__ __launch_bounds__(256, 2) void gemm_out(
    const float* __restrict__ bo, float* __restrict__ out)
{
    extern __shared__ __half gsm[];
    __half* sA = gsm;
    __half* sB = gsm + 2 * GTILE;

    const __half* Wp = gW + 3 * WELEM;

    const int tid = threadIdx.x, lane = tid & 31, warp = tid >> 5;
    const int m0 = blockIdx.y * 128, n0 = blockIdx.x * 128;
    const int wm = (warp & 1) * 64, wn = (warp >> 1) * 32;

    const __half* gA = gO + (size_t)m0 * DM;
    const __half* gB = Wp + (size_t)n0 * DM;

    float c[4][4][4];
    #pragma unroll
    for (int i = 0; i < 4; i++)
        #pragma unroll
        for (int j = 0; j < 4; j++)
            #pragma unroll
            for (int r = 0; r < 4; r++) c[i][j][r] = 0.0f;

    GEMM_LOAD_STAGE64(sA, sB, 0)
    CP_COMMIT();

    const int ar = lane & 15, achk = lane >> 4;
    const int br = lane & 7,  bchk = (lane >> 3) & 1;

    for (int kt = 0; kt < 16; kt++) {
        const int st = kt & 1;
        CP_WAIT0();
        __syncthreads();
        if (kt < 15) {
            GEMM_LOAD_STAGE64(sA + (st ^ 1) * GTILE, sB + (st ^ 1) * GTILE,
                              (kt + 1) * 64)
            CP_COMMIT();
        }
        GEMM_KSTEP64(0)
        GEMM_KSTEP64(1)
        GEMM_KSTEP64(2)
        GEMM_KSTEP64(3)
    }

    const int r0 = lane >> 2, cq = (lane & 3) * 2;
    #pragma unroll
    for (int mi = 0; mi < 4; mi++) {
        #pragma unroll
        for (int ni = 0; ni < 4; ni++) {
            int col = n0 + wn + ni * 8 + cq;
            float b0 = bo[col], b1 = bo[col + 1];
            #pragma unroll
            for (int half = 0; half < 2; half++) {
                int row = m0 + wm + mi * 16 + r0 + half * 8;
                float2 v = make_float2(c[mi][ni][half * 2 + 0] + b0,
                                       c[mi][ni][half * 2 + 1] + b1);
                *(float2*)&out[(size_t)row * DM + col] = v;
            }
        }
    }
}

// ---------------- flash attention -------------------------------------------
// S: Q fp16 x K fp16 (1 MMA). PV: P fp16 x V fp16 (1 MMA).
// XOR-swizzled smem: Q 128x64, KV 2 stages x 2 x 64x64. 49,152 B -> 2 CTAs/SM.
#define QTSZ   (128*64)              // elems per Q tile
#define KVTSZ  (64*64)               // elems per K/V tile
#define KVSTG  (2*KVTSZ)             // elems per KV stage [K, V]
#define FLASH_SMEM ((QTSZ + 2*KVSTG) * 2)   // bytes = 49152

__global__ __launch_bounds__(256, 2) void flash()
{
    extern __shared__ __half sm[];
    __half* sQ  = sm;                 // [128x64] swizzled
    __half* sKV = sm + QTSZ;          // [stage][K,V][64x64]

    const int tid = threadIdx.x, lane = tid & 31, warp = tid >> 5;
    const int bh = blockIdx.y, q0 = blockIdx.x * 128;
    const size_t base = (size_t)bh * NSEQ * HD;

    // Q tile: 1024 chunks; 4 per thread
    #pragma unroll
    for (int u = 0; u < 4; u++) {
        int id = tid + u * 256;
        int r = id >> 3, c8 = id & 7;
        cp16(&sQ[swz64(r, c8)], gQ + base + (size_t)(q0 + r) * HD + c8 * 8);
    }
    // KV stage 0: 2 x 512 chunks; 4 per thread
    #pragma unroll
    for (int u = 0; u < 4; u++) {
        int id = tid + u * 256;
        int t = id >> 9, rem = id & 511;
        int r = rem >> 3, c8 = rem & 7;
        size_t g = base + (size_t)r * HD + c8 * 8;
        const void* src = (t == 0) ? (const void*)(gK + g)
                                   : (const void*)(gV + g);
        cp16(&sKV[t * KVTSZ + swz64(r, c8)], src);
    }
    CP_COMMIT();

    float o[8][4];
    #pragma unroll
    for (int i = 0; i < 8; i++)
        #pragma unroll
        for (int j = 0; j < 4; j++) o[i][j] = 0.0f;
    float mr0 = -1e30f, mr1 = -1e30f, lr0 = 0.0f, lr1 = 0.0f;

    const int ar = lane & 15;
    const int achk = lane >> 4;          // A-operand chunk half
    const int br = lane & 7;
    const int bchk = (lane >> 3) & 1;    // B-operand chunk half

    for (int kt = 0; kt < NSEQ / 64; kt++) {
        const int st = kt & 1;
        CP_WAIT0();
        __syncthreads();
        if (kt < NSEQ / 64 - 1) {
            __half* d = sKV + (st ^ 1) * KVSTG;
            size_t kb = base + (size_t)(kt + 1) * 64 * HD;
            #pragma unroll
            for (int u = 0; u < 4; u++) {
                int id = tid + u * 256;
                int t = id >> 9, rem = id & 511;
                int r = rem >> 3, c8 = rem & 7;
                size_t g = kb + (size_t)r * HD + c8 * 8;
                const void* src = (t == 0) ? (const void*)(gK + g)
                                           : (const void*)(gV + g);
                cp16(&d[t * KVTSZ + swz64(r, c8)], src);
            }
            CP_COMMIT();
        }

        const __half* Ks = sKV + st * KVSTG;
        const __half* Vs = Ks + KVTSZ;

        float s[8][4];
        #pragma unroll
        for (int i = 0; i < 8; i++)
            #pragma unroll
            for (int j = 0; j < 4; j++) s[i][j] = 0.0f;

        // S = Q.K^T — 1 term, term-major over ni-quads
        #pragma unroll
        for (int kk = 0; kk < 4; kk++) {
            unsigned ah[4];
            int arow = warp * 16 + ar;
            int aoff = swz64(arow, kk * 2 + achk);
            ldm_x4(ah[0], ah[1], ah[2], ah[3], &sQ[aoff]);
            #pragma unroll
            for (int nh = 0; nh < 2; nh++) {
                unsigned kb4[4][2];
                #pragma unroll
                for (int nq = 0; nq < 4; nq++) {
                    int krow = (nh * 4 + nq) * 8 + br;
                    int koff = swz64(krow, kk * 2 + bchk);
                    ldm_x2(kb4[nq][0], kb4[nq][1], &Ks[koff]);
                }
                #pragma unroll
                for (int nq = 0; nq < 4; nq++)
                    mma16816h(s[nh * 4 + nq], ah[0], ah[1], ah[2], ah[3],
                              kb4[nq][0], kb4[nq][1]);
            }
        }

        float mx0 = -1e30f, mx1 = -1e30f;
        #pragma unroll
        for (int ni = 0; ni < 8; ni++) {
            mx0 = fmaxf(mx0, fmaxf(s[ni][0], s[ni][1]));
            mx1 = fmaxf(mx1, fmaxf(s[ni][2], s[ni][3]));
        }
        mx0 = fmaxf(mx0, __shfl_xor_sync(0xffffffffu, mx0, 1));
        mx0 = fmaxf(mx0, __shfl_xor_sync(0xffffffffu, mx0, 2));
        mx1 = fmaxf(mx1, __shfl_xor_sync(0xffffffffu, mx1, 1));
        mx1 = fmaxf(mx1, __shfl_xor_sync(0xffffffffu, mx1, 2));

        float nm0 = fmaxf(mr0, mx0), nm1 = fmaxf(mr1, mx1);
        float cr0 = __expf(mr0 - nm0), cr1 = __expf(mr1 - nm1);
        mr0 = nm0; mr1 = nm1;

        float sum0 = 0.0f, sum1 = 0.0f;
        #pragma unroll
        for (int ni = 0; ni < 8; ni++) {
            s[ni][0] = __expf(s[ni][0] - nm0);
            s[ni][1] = __expf(s[ni][1] - nm0);
            s[ni][2] = __expf(s[ni][2] - nm1);
            s[ni][3] = __expf(s[ni][3] - nm1);
            sum0 += s[ni][0] + s[ni][1];
            sum1 += s[ni][2] + s[ni][3];
        }
        sum0 += __shfl_xor_sync(0xffffffffu, sum0, 1);
        sum0 += __shfl_xor_sync(0xffffffffu, sum0, 2);
        sum1 += __shfl_xor_sync(0xffffffffu, sum1, 1);
        sum1 += __shfl_xor_sync(0xffffffffu, sum1, 2);
        lr0 = lr0 * cr0 + sum0;
        lr1 = lr1 * cr1 + sum1;
        #pragma unroll
        for (int dj = 0; dj < 8; dj++) {
            o[dj][0] *= cr0; o[dj][1] *= cr0;
            o[dj][2] *= cr1; o[dj][3] *= cr1;
        }

        // O += P(fp16) . V(fp16) — term-major over dj-quads
        #pragma unroll
        for (int kk = 0; kk < 4; kk++) {
            unsigned p0 = pack_h2(s[2*kk][0],   s[2*kk][1]);
            unsigned p1 = pack_h2(s[2*kk][2],   s[2*kk][3]);
            unsigned p2 = pack_h2(s[2*kk+1][0], s[2*kk+1][1]);
            unsigned p3 = pack_h2(s[2*kk+1][2], s[2*kk+1][3]);
            int vrow = kk * 16 + ar;
            #pragma unroll
            for (int dh = 0; dh < 2; dh++) {
                unsigned vb4[4][2];
                #pragma unroll
                for (int dq = 0; dq < 4; dq++) {
                    int voff = swz64(vrow, dh * 4 + dq);
                    ldm_x2t(vb4[dq][0], vb4[dq][1], &Vs[voff]);
                }
                #pragma unroll
                for (int dq = 0; dq < 4; dq++)
                    mma16816h(o[dh * 4 + dq], p0, p1, p2, p3,
                              vb4[dq][0], vb4[dq][1]);
            }
        }
    }

    const int b = bh >> 4, h = bh & 15;
    const int row0 = q0 + warp * 16 + (lane >> 2);
    const float inv0 = 1.0f / lr0, inv1 = 1.0f / lr1;
    const size_t rb = ((size_t)(b * NSEQ) + row0) * DM + h * HD;
    #pragma unroll
    for (int dj = 0; dj < 8; dj++) {
        int d = dj * 8 + (lane & 3) * 2;
        *(unsigned*)&gO[rb + d] = pack_h2(o[dj][0] * inv0, o[dj][1] * inv0);
        *(unsigned*)&gO[rb + (size_t)8 * DM + d] =
            pack_h2(o[dj][2] * inv1, o[dj][3] * inv1);
    }
}

// ---------------------------------------------------------------------------
extern "C" void kernel_launch(void* const* d_in, const int* in_sizes, int n_in,
                              void* d_out, int out_size)
{
    (void)in_sizes; (void)n_in; (void)out_size;
    const float* queries = (const float*)d_in[0];
    const float* keys    = (const float*)d_in[1];
    const float* values  = (const float*)d_in[2];
    const float* Wq = (const float*)d_in[3];
    const float* bq = (const float*)d_in[4];
    const float* Wk = (const float*)d_in[5];
    const float* bk = (const float*)d_in[6];
    const float* Wv = (const float*)d_in[7];
    const float* bv = (const float*)d_in[8];
    const float* Wo = (const float*)d_in[9];
    const float* bo = (const float*)d_in[10];
    float* out = (float*)d_out;

    cudaFuncSetAttribute(flash, cudaFuncAttributeMaxDynamicSharedMemorySize,
                         FLASH_SMEM);
    cudaFuncSetAttribute(gemm_qkv, cudaFuncAttributeMaxDynamicSharedMemorySize,
                         GSMEM);
    cudaFuncSetAttribute(gemm_out, cudaFuncAttributeMaxDynamicSharedMemorySize,
                         GSMEM);

    // fp32 -> fp16 (single launch)
    split_all<<<2048, 256>>>(queries, keys, values, Wq, Wk, Wv, Wo);

    // QKV projections
    gemm_qkv<<<dim3(DM / 128, MROWS / 128, 3), 256, GSMEM>>>(bq, bk, bv);

    // attention
    flash<<<dim3(NSEQ / 128, NB * NH), 256, FLASH_SMEM>>>();

    // output projection
    gemm_out<<<dim3(DM / 128, MROWS / 128), 256, GSMEM>>>(bo, out);
}